// round 12
// baseline (speedup 1.0000x reference)
#include <cuda_runtime.h>
#include <cuda_fp16.h>
#include <math.h>
#include <stdint.h>

// Problem constants
#define BATCH 4
#define NTOK 4096
#define DIM 1024
#define NHEAD 16
#define HD 64
#define MROWS (BATCH * NTOK)          // 16384
#define SCALE 0.125f                  // HD^-0.5
#define NCHUNK 4

// ---------------------------------------------------------------------------
// Scratch buffers
// ---------------------------------------------------------------------------
__device__ __half g_x_h [MROWS * DIM];
__device__ __half g_hq_h[MROWS * DIM];
__device__ __half g_hk_h[MROWS * DIM];
__device__ __half g_y_h [MROWS * DIM];
__device__ __half g_q [MROWS * DIM];
__device__ __half g_k [MROWS * DIM];
__device__ __half g_v [MROWS * DIM];
__device__ __half g_g [MROWS * DIM];
__device__ float g_A [BATCH * NHEAD * HD * HD];
__device__ float g_z [BATCH * NHEAD * HD];
__device__ float g_Ap[NCHUNK * BATCH * NHEAD * HD * HD];
__device__ float g_zp[NCHUNK * BATCH * NHEAD * HD];
__device__ __half g_wcat[4 * DIM * DIM];   // concatenated first-layer weights
__device__ __half g_w2  [3 * DIM * DIM];   // q_w2, k_w2, p_w

// ---------------------------------------------------------------------------
// PTX helpers (sm_80+ portable)
// ---------------------------------------------------------------------------
__device__ __forceinline__ uint32_t smem_u32(const void* p) {
    uint32_t a;
    asm("{ .reg .u64 t; cvta.to.shared.u64 t, %1; cvt.u32.u64 %0, t; }" : "=r"(a) : "l"(p));
    return a;
}
#define SWZ(o) ((o) ^ (((o) >> 3) & 0x70))

__device__ __forceinline__ void cp16(uint32_t saddr, const void* g) {
    asm volatile("cp.async.cg.shared.global [%0], [%1], 16;" :: "r"(saddr), "l"(g));
}
#define CP_COMMIT() asm volatile("cp.async.commit_group;" ::: "memory")
#define CP_WAIT(N)  asm volatile("cp.async.wait_group %0;" :: "n"(N) : "memory")

#define LDSM4(r, a) \
    asm volatile("ldmatrix.sync.aligned.m8n8.x4.shared.b16 {%0,%1,%2,%3}, [%4];" \
        : "=r"((r)[0]), "=r"((r)[1]), "=r"((r)[2]), "=r"((r)[3]) : "r"(a))

#define MMA16816F(c, a, b) \
    asm volatile("mma.sync.aligned.m16n8k16.row.col.f32.f16.f16.f32 " \
        "{%0,%1,%2,%3}, {%4,%5,%6,%7}, {%8,%9}, {%0,%1,%2,%3};" \
        : "+f"((c)[0]), "+f"((c)[1]), "+f"((c)[2]), "+f"((c)[3]) \
        : "r"((a)[0]), "r"((a)[1]), "r"((a)[2]), "r"((a)[3]), \
          "r"((b)[0]), "r"((b)[1]))

// ---------------------------------------------------------------------------
// Activations
// ---------------------------------------------------------------------------
__device__ __forceinline__ float gelu_f(float x) {
    return 0.5f * x * (1.0f + erff(x * 0.70710678118654752440f));
}
__device__ __forceinline__ float softplus_f(float x) {
    return fmaxf(x, 0.0f) + log1pf(__expf(-fabsf(x)));
}
__device__ __forceinline__ uint32_t pack2h(float a, float b) {
    __half2 h = __halves2half2(__float2half_rn(a), __float2half_rn(b));
    return *(uint32_t*)&h;
}

// ---------------------------------------------------------------------------
// fp32 -> fp16 convert, 8 elems/thread/iter
// ---------------------------------------------------------------------------
__global__ __launch_bounds__(256)
void conv_f2h_w(const float4* __restrict__ src, uint4* __restrict__ dst, int n8)
{
    const int stride = gridDim.x * blockDim.x;
    for (int i = blockIdx.x * blockDim.x + threadIdx.x; i < n8; i += stride) {
        float4 a = src[2 * i];
        float4 b = src[2 * i + 1];
        uint4 d;
        d.x = pack2h(a.x, a.y);
        d.y = pack2h(a.z, a.w);
        d.z = pack2h(b.x, b.y);
        d.w = pack2h(b.z, b.w);
        dst[i] = d;
    }
}

// ---------------------------------------------------------------------------
// Shared GEMM mainloop (device inline)
// ---------------------------------------------------------------------------
#define TILE_B 16384
#define STAGE_B (2 * TILE_B)
#define NSTAGE 3
#define GSMEM_TOTAL (NSTAGE * STAGE_B)  // 98304

__device__ __forceinline__ void gemm_core(
    const __half* __restrict__ A, const __half* __restrict__ Wh,
    uint32_t sb, int t, int m0, int n0, float acc[2][8][4])
{
    const int lane = t & 31;
    const int w    = t >> 5;
    const int wm   = w & 3;
    const int wn   = w >> 2;
    const int lrow = t >> 3;
    const int lu   = t & 7;

    auto issue = [&](int stage, int kc) {
        const uint32_t sbase = sb + stage * STAGE_B;
        const int kbase = kc * 64 + lu * 8;
#pragma unroll
        for (int i = 0; i < 4; i++) {
            const int row = lrow + i * 32;
            const uint32_t soff = SWZ((uint32_t)(row * 128 + lu * 16));
            cp16(sbase + soff,          A  + (size_t)(m0 + row) * DIM + kbase);
            cp16(sbase + TILE_B + soff, Wh + (size_t)(n0 + row) * DIM + kbase);
        }
        CP_COMMIT();
    };

    issue(0, 0);
    issue(1, 1);

    const int g  = lane >> 3;
    const int rr = lane & 7;

    for (int kc = 0; kc < 16; kc++) {
        if (kc == 15) { CP_WAIT(0); } else { CP_WAIT(1); }
        __syncthreads();
        if (kc + 2 < 16) issue((kc + 2) % NSTAGE, kc + 2);

        const uint32_t st = sb + (kc % NSTAGE) * STAGE_B;
#pragma unroll
        for (int kk = 0; kk < 4; kk++) {
            const int ku = kk * 2 + (g >> 1);
            uint32_t ah[2][4];
#pragma unroll
            for (int im = 0; im < 2; im++) {
                const int row = wm * 32 + im * 16 + (g & 1) * 8 + rr;
                const uint32_t off = SWZ((uint32_t)(row * 128 + ku * 16));
                LDSM4(ah[im], st + off);
            }
            uint32_t bh[8][2];
#pragma unroll
            for (int in2 = 0; in2 < 4; in2++) {
                const int row = wn * 64 + in2 * 16 + (g & 1) * 8 + rr;
                const uint32_t off = SWZ((uint32_t)(row * 128 + ku * 16));
                uint32_t qh[4];
                LDSM4(qh, st + TILE_B + off);
                bh[2 * in2][0] = qh[0]; bh[2 * in2][1] = qh[2];
                bh[2 * in2 + 1][0] = qh[1]; bh[2 * in2 + 1][1] = qh[3];
            }
#pragma unroll
            for (int im = 0; im < 2; im++)
#pragma unroll
                for (int in = 0; in < 8; in++)
                    MMA16816F(acc[im][in], ah[im], bh[in]);
        }
    }
}

// ---------------------------------------------------------------------------
// Standard GEMM: C = act(A @ W^T + bias), fp32 or fp16 out
// ---------------------------------------------------------------------------
__global__ __launch_bounds__(256, 2)
void gemm_mma(const __half* __restrict__ A, const __half* __restrict__ Wh,
              const float* __restrict__ bias, int act, int outmode,
              float* __restrict__ Cf, __half* __restrict__ Ch)
{
    extern __shared__ char smem[];
    const uint32_t sb = smem_u32(smem);
    const int t  = threadIdx.x;
    const int m0 = blockIdx.y * 128;
    const int n0 = blockIdx.x * 128;

    float acc[2][8][4];
#pragma unroll
    for (int im = 0; im < 2; im++)
#pragma unroll
        for (int in = 0; in < 8; in++)
#pragma unroll
            for (int j = 0; j < 4; j++) acc[im][in][j] = 0.0f;

    gemm_core(A, Wh, sb, t, m0, n0, acc);

    const int lane = t & 31;
    const int w    = t >> 5;
    const int wm   = w & 3;
    const int wn   = w >> 2;
    const int r0 = lane >> 2;
    const int c0 = (lane & 3) * 2;
#pragma unroll
    for (int im = 0; im < 2; im++) {
#pragma unroll
        for (int in = 0; in < 8; in++) {
            const int ncol = n0 + wn * 64 + in * 8 + c0;
            const float b0 = __ldg(&bias[ncol]);
            const float b1 = __ldg(&bias[ncol + 1]);
#pragma unroll
            for (int half = 0; half < 2; half++) {
                const int mrow = m0 + wm * 32 + im * 16 + r0 + half * 8;
                float v0 = acc[im][in][half * 2]     + b0;
                float v1 = acc[im][in][half * 2 + 1] + b1;
                if (act == 1)      { v0 = gelu_f(v0);     v1 = gelu_f(v1); }
                else if (act == 2) { v0 = softplus_f(v0); v1 = softplus_f(v1); }
                if (outmode == 0) {
                    *(float2*)(Cf + (size_t)mrow * DIM + ncol) = make_float2(v0, v1);
                } else {
                    *(__half2*)(Ch + (size_t)mrow * DIM + ncol) =
                        __halves2half2(__float2half_rn(v0), __float2half_rn(v1));
                }
            }
        }
    }
}

// ---------------------------------------------------------------------------
// Fused first-layer GEMM: N=4096 over concatenated weights (q1,k1,v,g)
// ---------------------------------------------------------------------------
__global__ __launch_bounds__(256, 2)
void gemm_mma4(const __half* __restrict__ A, const __half* __restrict__ Wcat,
               const float* __restrict__ bq, const float* __restrict__ bk,
               const float* __restrict__ bv, const float* __restrict__ bg,
               __half* __restrict__ dq, __half* __restrict__ dk,
               __half* __restrict__ dv, __half* __restrict__ dg)
{
    extern __shared__ char smem[];
    const uint32_t sb = smem_u32(smem);
    const int t  = threadIdx.x;
    const int m0 = blockIdx.y * 128;
    const int n0 = blockIdx.x * 128;          // global column in [0, 4096)
    const int seg = blockIdx.x >> 3;          // 8 CTAs per 1024-col segment
    const int nloc0 = n0 & 1023;

    const float* bias = (seg == 0) ? bq : (seg == 1) ? bk : (seg == 2) ? bv : bg;
    __half* dst = (seg == 0) ? dq : (seg == 1) ? dk : (seg == 2) ? dv : dg;

    float acc[2][8][4];
#pragma unroll
    for (int im = 0; im < 2; im++)
#pragma unroll
        for (int in = 0; in < 8; in++)
#pragma unroll
            for (int j = 0; j < 4; j++) acc[im][in][j] = 0.0f;

    gemm_core(A, Wcat, sb, t, m0, n0, acc);

    const int lane = t & 31;
    const int w    = t >> 5;
    const int wm   = w & 3;
    const int wn   = w >> 2;
    const int r0 = lane >> 2;
    const int c0 = (lane & 3) * 2;
#pragma unroll
    for (int im = 0; im < 2; im++) {
#pragma unroll
        for (int in = 0; in < 8; in++) {
            const int ncol = nloc0 + wn * 64 + in * 8 + c0;
            const float b0 = __ldg(&bias[ncol]);
            const float b1 = __ldg(&bias[ncol + 1]);
#pragma unroll
            for (int half = 0; half < 2; half++) {
                const int mrow = m0 + wm * 32 + im * 16 + r0 + half * 8;
                float v0 = gelu_f(acc[im][in][half * 2]     + b0);
                float v1 = gelu_f(acc[im][in][half * 2 + 1] + b1);
                *(__half2*)(dst + (size_t)mrow * DIM + ncol) =
                    __halves2half2(__float2half_rn(v0), __float2half_rn(v1));
            }
        }
    }
}

// ---------------------------------------------------------------------------
// Attention pass 1 (partial) — fp16 q/k inputs, fp32 compute
// ---------------------------------------------------------------------------
__global__ __launch_bounds__(512)
void attn_pass1p(const __half* __restrict__ q, const __half* __restrict__ k,
                 float* __restrict__ Ap, float* __restrict__ Zp)
{
    const int bh = blockIdx.x;
    const int ch = blockIdx.y;
    const int b  = bh >> 4;
    const int h  = bh & 15;
    const __half* qb = q + (size_t)b * NTOK * DIM + h * HD;
    const __half* kb = k + (size_t)b * NTOK * DIM + h * HD;

    __shared__ float qs[64][64];
    __shared__ float ks[64][64];
    __shared__ float ksum[64];

    const int t  = threadIdx.x;
    const int n  = t >> 3;
    const int m0 = (t & 7) << 3;
    const int lr = t >> 3;
    const int lc = (t & 7) << 3;

    float acc[8] = {0, 0, 0, 0, 0, 0, 0, 0};
    float zacc = 0.0f;
    const bool zowner = ((t & 7) == 0);

    const int cbeg = ch * (NTOK / NCHUNK);
    const int cend = cbeg + (NTOK / NCHUNK);
    for (int c0 = cbeg; c0 < cend; c0 += 64) {
        const uint4 qr = *(const uint4*)(qb + (size_t)(c0 + lr) * DIM + lc);
        const uint4 kr = *(const uint4*)(kb + (size_t)(c0 + lr) * DIM + lc);
        __syncthreads();
        {
            const __half2* qp = (const __half2*)&qr;
            const __half2* kp = (const __half2*)&kr;
#pragma unroll
            for (int j = 0; j < 4; j++) {
                float2 qf = __half22float2(qp[j]);
                float2 kf = __half22float2(kp[j]);
                qs[lr][lc + 2 * j]     = qf.x;
                qs[lr][lc + 2 * j + 1] = qf.y;
                ks[lr][lc + 2 * j]     = kf.x;
                ks[lr][lc + 2 * j + 1] = kf.y;
            }
        }
        __syncthreads();
        if (t < 64) {
            float s = 0.0f;
#pragma unroll
            for (int m = 0; m < 64; m++) s += ks[t][(m + t) & 63];
            ksum[t] = s;
        }
        __syncthreads();

#pragma unroll 4
        for (int c = 0; c < 64; c++) {
            float qv = qs[c][n];
            float4 k4a = *(const float4*)&ks[c][m0];
            float4 k4b = *(const float4*)&ks[c][m0 + 4];
            acc[0] += qv * k4a.x; acc[1] += qv * k4a.y;
            acc[2] += qv * k4a.z; acc[3] += qv * k4a.w;
            acc[4] += qv * k4b.x; acc[5] += qv * k4b.y;
            acc[6] += qv * k4b.z; acc[7] += qv * k4b.w;
            if (zowner) zacc += qv * ksum[c];
        }
    }

    float* Abh = Ap + ((size_t)ch * 64 + bh) * HD * HD;
#pragma unroll
    for (int j = 0; j < 8; j++)
        Abh[(m0 + j) * HD + n] = acc[j];
    if (zowner)
        Zp[((size_t)ch * 64 + bh) * HD + n] = zacc;
}

__global__ __launch_bounds__(256)
void attn_reduce(const float* __restrict__ Ap, const float* __restrict__ Zp,
                 float* __restrict__ gA, float* __restrict__ gZ)
{
    const int bh = blockIdx.x;
    const int t  = threadIdx.x;
    for (int i = t; i < HD * HD; i += 256) {
        float s = 0.0f;
#pragma unroll
        for (int c = 0; c < NCHUNK; c++)
            s += Ap[((size_t)c * 64 + bh) * HD * HD + i];
        gA[(size_t)bh * HD * HD + i] = s;
    }
    if (t < HD) {
        float s = 0.0f;
#pragma unroll
        for (int c = 0; c < NCHUNK; c++)
            s += Zp[((size_t)c * 64 + bh) * HD + t];
        gZ[bh * HD + t] = 1.0f / (SCALE * s + (float)DIM);
    }
}

// ---------------------------------------------------------------------------
// Attention pass 2 (per-batch launch): grid (NHEAD, 64)
// ---------------------------------------------------------------------------
__global__ __launch_bounds__(256)
void attn_pass2b(const __half* __restrict__ v, const __half* __restrict__ gg,
                 const float* __restrict__ gA, const float* __restrict__ gZ,
                 __half* __restrict__ Yh, int b)
{
    const int h  = blockIdx.x;
    const int bh = b * NHEAD + h;
    const int c0 = blockIdx.y * 64;

    __shared__ float As[HD * HD];
    __shared__ float vs[64][64];
    __shared__ float zs[64];

    const int t = threadIdx.x;

    const float4* Asrc = (const float4*)(gA + (size_t)bh * HD * HD);
#pragma unroll
    for (int i = t; i < HD * HD / 4; i += 256)
        ((float4*)As)[i] = Asrc[i];
    if (t < 64) zs[t] = gZ[bh * HD + t];

    {
        const int lr = t >> 2;
        const int lc = (t & 3) << 4;
        const __half* vrow = v + (size_t)(b * NTOK + c0 + lr) * DIM + h * HD + lc;
        uint4 r0 = *(const uint4*)(vrow);
        uint4 r1 = *(const uint4*)(vrow + 8);
        const __half2* p0 = (const __half2*)&r0;
        const __half2* p1 = (const __half2*)&r1;
#pragma unroll
        for (int j = 0; j < 4; j++) {
            float2 f0 = __half22float2(p0[j]);
            float2 f1 = __half22float2(p1[j]);
            vs[lr][lc + 2 * j]         = f0.x;
            vs[lr][lc + 2 * j + 1]     = f0.y;
            vs[lr][lc + 8 + 2 * j]     = f1.x;
            vs[lr][lc + 8 + 2 * j + 1] = f1.y;
        }
    }
    __syncthreads();

    const int nloc = t & 63;
    const int dgrp = t >> 6;

    for (int d = dgrp; d < 64; d += 4) {
        float accv = 0.0f;
#pragma unroll
        for (int m = 0; m < 64; m++)
            accv += As[m * 64 + nloc] * vs[d][m];
        const int tok = c0 + d;
        float val = (SCALE * accv + vs[d][nloc]) * zs[nloc];
        val *= __half2float(gg[(size_t)(b * NTOK + tok) * DIM + h * HD + nloc]);
        const int row = b * NTOK + h * 256 + (tok >> 4);
        const int col = ((tok & 15) << 6) + nloc;
        Yh[(size_t)row * DIM + col] = __float2half_rn(val);
    }
}

// ---------------------------------------------------------------------------
// Launch — capture-safe fork/join DAG
// ---------------------------------------------------------------------------
extern "C" void kernel_launch(void* const* d_in, const int* in_sizes, int n_in,
                              void* d_out, int out_size)
{
    const float* x    = (const float*)d_in[0];
    const float* q_w1 = (const float*)d_in[1];
    const float* q_b1 = (const float*)d_in[2];
    const float* q_w2 = (const float*)d_in[3];
    const float* q_b2 = (const float*)d_in[4];
    const float* k_w1 = (const float*)d_in[5];
    const float* k_b1 = (const float*)d_in[6];
    const float* k_w2 = (const float*)d_in[7];
    const float* k_b2 = (const float*)d_in[8];
    const float* v_w  = (const float*)d_in[9];
    const float* v_b  = (const float*)d_in[10];
    const float* g_w  = (const float*)d_in[11];
    const float* g_b  = (const float*)d_in[12];
    const float* p_w  = (const float*)d_in[13];
    const float* p_b  = (const float*)d_in[14];
    float* out = (float*)d_out;

    __half *xh, *hqh, *hkh, *yh, *wcat, *w2, *qb, *kb, *vb, *gb;
    float *Ab, *zb, *Apb, *zpb;
    cudaGetSymbolAddress((void**)&xh,   g_x_h);
    cudaGetSymbolAddress((void**)&hqh,  g_hq_h);
    cudaGetSymbolAddress((void**)&hkh,  g_hk_h);
    cudaGetSymbolAddress((void**)&yh,   g_y_h);
    cudaGetSymbolAddress((void**)&wcat, g_wcat);
    cudaGetSymbolAddress((void**)&w2,   g_w2);
    cudaGetSymbolAddress((void**)&qb,   g_q);
    cudaGetSymbolAddress((void**)&kb,   g_k);
    cudaGetSymbolAddress((void**)&vb,   g_v);
    cudaGetSymbolAddress((void**)&gb,   g_g);
    cudaGetSymbolAddress((void**)&Ab,   g_A);
    cudaGetSymbolAddress((void**)&zb,   g_z);
    cudaGetSymbolAddress((void**)&Apb,  g_Ap);
    cudaGetSymbolAddress((void**)&zpb,  g_zp);

    static bool init_done = false;
    static cudaStream_t s1, s2, s3;
    static cudaEvent_t ev_fork, ev_c1, ev_c2, ev_c3, ev_mega, ev_qw2, ev_kw2,
                       ev_pw, ev_k2, ev_done;
    static cudaEvent_t ev_p2[BATCH];
    if (!init_done) {
        cudaFuncSetAttribute(gemm_mma,  cudaFuncAttributeMaxDynamicSharedMemorySize, GSMEM_TOTAL);
        cudaFuncSetAttribute(gemm_mma4, cudaFuncAttributeMaxDynamicSharedMemorySize, GSMEM_TOTAL);
        cudaStreamCreateWithFlags(&s1, cudaStreamNonBlocking);
        cudaStreamCreateWithFlags(&s2, cudaStreamNonBlocking);
        cudaStreamCreateWithFlags(&s3, cudaStreamNonBlocking);
        cudaEventCreateWithFlags(&ev_fork, cudaEventDisableTiming);
        cudaEventCreateWithFlags(&ev_c1,   cudaEventDisableTiming);
        cudaEventCreateWithFlags(&ev_c2,   cudaEventDisableTiming);
        cudaEventCreateWithFlags(&ev_c3,   cudaEventDisableTiming);
        cudaEventCreateWithFlags(&ev_mega, cudaEventDisableTiming);
        cudaEventCreateWithFlags(&ev_qw2,  cudaEventDisableTiming);
        cudaEventCreateWithFlags(&ev_kw2,  cudaEventDisableTiming);
        cudaEventCreateWithFlags(&ev_pw,   cudaEventDisableTiming);
        cudaEventCreateWithFlags(&ev_k2,   cudaEventDisableTiming);
        cudaEventCreateWithFlags(&ev_done, cudaEventDisableTiming);
        for (int b = 0; b < BATCH; b++)
            cudaEventCreateWithFlags(&ev_p2[b], cudaEventDisableTiming);
        init_done = true;
    }

    const int WSZ = DIM * DIM;
    const int W8  = WSZ / 8;

    // === fork: all side streams join the capture FIRST ===
    cudaEventRecord(ev_fork, 0);
    cudaStreamWaitEvent(s1, ev_fork, 0);
    cudaStreamWaitEvent(s2, ev_fork, 0);
    cudaStreamWaitEvent(s3, ev_fork, 0);

    // --- conversions ---
    // s1: q_w1 (seg0) + g_w (seg3)
    conv_f2h_w<<<592, 256, 0, s1>>>((const float4*)q_w1, (uint4*)(wcat), W8);
    conv_f2h_w<<<592, 256, 0, s1>>>((const float4*)g_w,  (uint4*)(wcat + 3 * (size_t)WSZ), W8);
    cudaEventRecord(ev_c1, s1);
    // s2: k_w1 (seg1), then q_w2
    conv_f2h_w<<<592, 256, 0, s2>>>((const float4*)k_w1, (uint4*)(wcat + 1 * (size_t)WSZ), W8);
    cudaEventRecord(ev_c2, s2);
    conv_f2h_w<<<592, 256, 0, s2>>>((const float4*)q_w2, (uint4*)(w2), W8);
    cudaEventRecord(ev_qw2, s2);
    // s3: v_w (seg2), then k_w2, p_w
    conv_f2h_w<<<592, 256, 0, s3>>>((const float4*)v_w,  (uint4*)(wcat + 2 * (size_t)WSZ), W8);
    cudaEventRecord(ev_c3, s3);
    conv_f2h_w<<<592, 256, 0, s3>>>((const float4*)k_w2, (uint4*)(w2 + 1 * (size_t)WSZ), W8);
    cudaEventRecord(ev_kw2, s3);
    conv_f2h_w<<<592, 256, 0, s3>>>((const float4*)p_w,  (uint4*)(w2 + 2 * (size_t)WSZ), W8);
    cudaEventRecord(ev_pw, s3);
    // s0: x (big, critical)
    conv_f2h_w<<<2048, 256>>>((const float4*)x, (uint4*)xh, MROWS * DIM / 8);

    // --- fused first-layer GEMM (s0) ---
    cudaStreamWaitEvent(0, ev_c1, 0);
    cudaStreamWaitEvent(0, ev_c2, 0);
    cudaStreamWaitEvent(0, ev_c3, 0);
    gemm_mma4<<<dim3(4 * DIM / 128, MROWS / 128), 256, GSMEM_TOTAL>>>(
        xh, wcat, q_b1, k_b1, v_b, g_b, hqh, hkh, vb, gb);
    cudaEventRecord(ev_mega, 0);

    // --- second layers ---
    cudaStreamWaitEvent(0, ev_qw2, 0);
    gemm_mma<<<dim3(DIM / 128, MROWS / 128), 256, GSMEM_TOTAL>>>(
        hqh, w2, q_b2, 2, 1, nullptr, qb);
    cudaStreamWaitEvent(s1, ev_mega, 0);
    cudaStreamWaitEvent(s1, ev_kw2, 0);
    gemm_mma<<<dim3(DIM / 128, MROWS / 128), 256, GSMEM_TOTAL, s1>>>(
        hkh, w2 + (size_t)WSZ, k_b2, 2, 1, nullptr, kb);
    cudaEventRecord(ev_k2, s1);

    // --- attention pass 1 + reduce (s0) ---
    cudaStreamWaitEvent(0, ev_k2, 0);
    attn_pass1p<<<dim3(BATCH * NHEAD, NCHUNK), 512>>>(qb, kb, Apb, zpb);
    attn_reduce<<<BATCH * NHEAD, 256>>>(Apb, zpb, Ab, zb);

    // --- per-batch pass2 (s0) + pipelined final projection (s1) ---
    cudaStreamWaitEvent(s1, ev_pw, 0);
    for (int b = 0; b < BATCH; b++) {
        attn_pass2b<<<dim3(NHEAD, NTOK / 64), 256>>>(vb, gb, Ab, zb, yh, b);
        cudaEventRecord(ev_p2[b], 0);
        cudaStreamWaitEvent(s1, ev_p2[b], 0);
        gemm_mma<<<dim3(DIM / 128, NTOK / 128), 256, GSMEM_TOTAL, s1>>>(
            yh + (size_t)b * NTOK * DIM, w2 + 2 * (size_t)WSZ, p_b, 0, 0,
            out + (size_t)b * NTOK * DIM, nullptr);
    }
    cudaEventRecord(ev_done, s1);
    cudaStreamWaitEvent(0, ev_done, 0);
}

// round 13
// speedup vs baseline: 1.0084x; 1.0084x over previous
#include <cuda_runtime.h>
#include <cuda_fp16.h>
#include <math.h>
#include <stdint.h>

// Problem constants
#define BATCH 4
#define NTOK 4096
#define DIM 1024
#define NHEAD 16
#define HD 64
#define MROWS (BATCH * NTOK)          // 16384
#define SCALE 0.125f                  // HD^-0.5
#define NCHUNK 4

// ---------------------------------------------------------------------------
// Scratch buffers
// ---------------------------------------------------------------------------
__device__ __half g_x_h [MROWS * DIM];
__device__ __half g_hq_h[MROWS * DIM];
__device__ __half g_hk_h[MROWS * DIM];
__device__ __half g_y_h [MROWS * DIM];
__device__ __half g_q [MROWS * DIM];
__device__ __half g_k [MROWS * DIM];
__device__ __half g_v [MROWS * DIM];
__device__ __half g_g [MROWS * DIM];
__device__ float g_A [BATCH * NHEAD * HD * HD];
__device__ float g_z [BATCH * NHEAD * HD];
__device__ float g_Ap[NCHUNK * BATCH * NHEAD * HD * HD];
__device__ float g_zp[NCHUNK * BATCH * NHEAD * HD];
__device__ __half g_wcat[4 * DIM * DIM];   // q_w1 | k_w1 | v_w | g_w
__device__ __half g_w2  [2 * DIM * DIM];   // q_w2 | k_w2
__device__ __half g_wp  [DIM * DIM];       // p_w

// ---------------------------------------------------------------------------
// PTX helpers (sm_80+ portable)
// ---------------------------------------------------------------------------
__device__ __forceinline__ uint32_t smem_u32(const void* p) {
    uint32_t a;
    asm("{ .reg .u64 t; cvta.to.shared.u64 t, %1; cvt.u32.u64 %0, t; }" : "=r"(a) : "l"(p));
    return a;
}
#define SWZ(o) ((o) ^ (((o) >> 3) & 0x70))

__device__ __forceinline__ void cp16(uint32_t saddr, const void* g) {
    asm volatile("cp.async.cg.shared.global [%0], [%1], 16;" :: "r"(saddr), "l"(g));
}
#define CP_COMMIT() asm volatile("cp.async.commit_group;" ::: "memory")
#define CP_WAIT(N)  asm volatile("cp.async.wait_group %0;" :: "n"(N) : "memory")

#define LDSM4(r, a) \
    asm volatile("ldmatrix.sync.aligned.m8n8.x4.shared.b16 {%0,%1,%2,%3}, [%4];" \
        : "=r"((r)[0]), "=r"((r)[1]), "=r"((r)[2]), "=r"((r)[3]) : "r"(a))

#define MMA16816F(c, a, b) \
    asm volatile("mma.sync.aligned.m16n8k16.row.col.f32.f16.f16.f32 " \
        "{%0,%1,%2,%3}, {%4,%5,%6,%7}, {%8,%9}, {%0,%1,%2,%3};" \
        : "+f"((c)[0]), "+f"((c)[1]), "+f"((c)[2]), "+f"((c)[3]) \
        : "r"((a)[0]), "r"((a)[1]), "r"((a)[2]), "r"((a)[3]), \
          "r"((b)[0]), "r"((b)[1]))

// ---------------------------------------------------------------------------
// Activations
// ---------------------------------------------------------------------------
__device__ __forceinline__ float gelu_f(float x) {
    return 0.5f * x * (1.0f + erff(x * 0.70710678118654752440f));
}
__device__ __forceinline__ float softplus_f(float x) {
    return fmaxf(x, 0.0f) + log1pf(__expf(-fabsf(x)));
}
__device__ __forceinline__ uint32_t pack2h(float a, float b) {
    __half2 h = __halves2half2(__float2half_rn(a), __float2half_rn(b));
    return *(uint32_t*)&h;
}

// ---------------------------------------------------------------------------
// fp32 -> fp16 convert, 8 elems/thread/iter
// ---------------------------------------------------------------------------
__global__ __launch_bounds__(256)
void conv_f2h_w(const float4* __restrict__ src, uint4* __restrict__ dst, int n8)
{
    const int stride = gridDim.x * blockDim.x;
    for (int i = blockIdx.x * blockDim.x + threadIdx.x; i < n8; i += stride) {
        float4 a = src[2 * i];
        float4 b = src[2 * i + 1];
        uint4 d;
        d.x = pack2h(a.x, a.y);
        d.y = pack2h(a.z, a.w);
        d.z = pack2h(b.x, b.y);
        d.w = pack2h(b.z, b.w);
        dst[i] = d;
    }
}

// ---------------------------------------------------------------------------
// Shared GEMM mainloop (device inline)
// ---------------------------------------------------------------------------
#define TILE_B 16384
#define STAGE_B (2 * TILE_B)
#define NSTAGE 3
#define GSMEM_TOTAL (NSTAGE * STAGE_B)  // 98304

__device__ __forceinline__ void gemm_core(
    const __half* __restrict__ A, const __half* __restrict__ Wh,
    uint32_t sb, int t, int m0, int n0, float acc[2][8][4])
{
    const int lane = t & 31;
    const int w    = t >> 5;
    const int wm   = w & 3;
    const int wn   = w >> 2;
    const int lrow = t >> 3;
    const int lu   = t & 7;

    auto issue = [&](int stage, int kc) {
        const uint32_t sbase = sb + stage * STAGE_B;
        const int kbase = kc * 64 + lu * 8;
#pragma unroll
        for (int i = 0; i < 4; i++) {
            const int row = lrow + i * 32;
            const uint32_t soff = SWZ((uint32_t)(row * 128 + lu * 16));
            cp16(sbase + soff,          A  + (size_t)(m0 + row) * DIM + kbase);
            cp16(sbase + TILE_B + soff, Wh + (size_t)(n0 + row) * DIM + kbase);
        }
        CP_COMMIT();
    };

    issue(0, 0);
    issue(1, 1);

    const int g  = lane >> 3;
    const int rr = lane & 7;

    for (int kc = 0; kc < 16; kc++) {
        if (kc == 15) { CP_WAIT(0); } else { CP_WAIT(1); }
        __syncthreads();
        if (kc + 2 < 16) issue((kc + 2) % NSTAGE, kc + 2);

        const uint32_t st = sb + (kc % NSTAGE) * STAGE_B;
#pragma unroll
        for (int kk = 0; kk < 4; kk++) {
            const int ku = kk * 2 + (g >> 1);
            uint32_t ah[2][4];
#pragma unroll
            for (int im = 0; im < 2; im++) {
                const int row = wm * 32 + im * 16 + (g & 1) * 8 + rr;
                const uint32_t off = SWZ((uint32_t)(row * 128 + ku * 16));
                LDSM4(ah[im], st + off);
            }
            uint32_t bh[8][2];
#pragma unroll
            for (int in2 = 0; in2 < 4; in2++) {
                const int row = wn * 64 + in2 * 16 + (g & 1) * 8 + rr;
                const uint32_t off = SWZ((uint32_t)(row * 128 + ku * 16));
                uint32_t qh[4];
                LDSM4(qh, st + TILE_B + off);
                bh[2 * in2][0] = qh[0]; bh[2 * in2][1] = qh[2];
                bh[2 * in2 + 1][0] = qh[1]; bh[2 * in2 + 1][1] = qh[3];
            }
#pragma unroll
            for (int im = 0; im < 2; im++)
#pragma unroll
                for (int in = 0; in < 8; in++)
                    MMA16816F(acc[im][in], ah[im], bh[in]);
        }
    }
}

// ---------------------------------------------------------------------------
// Standard GEMM: C = act(A @ W^T + bias), fp32 or fp16 out
// ---------------------------------------------------------------------------
__global__ __launch_bounds__(256, 2)
void gemm_mma(const __half* __restrict__ A, const __half* __restrict__ Wh,
              const float* __restrict__ bias, int act, int outmode,
              float* __restrict__ Cf, __half* __restrict__ Ch)
{
    extern __shared__ char smem[];
    const uint32_t sb = smem_u32(smem);
    const int t  = threadIdx.x;
    const int m0 = blockIdx.y * 128;
    const int n0 = blockIdx.x * 128;

    float acc[2][8][4];
#pragma unroll
    for (int im = 0; im < 2; im++)
#pragma unroll
        for (int in = 0; in < 8; in++)
#pragma unroll
            for (int j = 0; j < 4; j++) acc[im][in][j] = 0.0f;

    gemm_core(A, Wh, sb, t, m0, n0, acc);

    const int lane = t & 31;
    const int w    = t >> 5;
    const int wm   = w & 3;
    const int wn   = w >> 2;
    const int r0 = lane >> 2;
    const int c0 = (lane & 3) * 2;
#pragma unroll
    for (int im = 0; im < 2; im++) {
#pragma unroll
        for (int in = 0; in < 8; in++) {
            const int ncol = n0 + wn * 64 + in * 8 + c0;
            const float b0 = __ldg(&bias[ncol]);
            const float b1 = __ldg(&bias[ncol + 1]);
#pragma unroll
            for (int half = 0; half < 2; half++) {
                const int mrow = m0 + wm * 32 + im * 16 + r0 + half * 8;
                float v0 = acc[im][in][half * 2]     + b0;
                float v1 = acc[im][in][half * 2 + 1] + b1;
                if (act == 1)      { v0 = gelu_f(v0);     v1 = gelu_f(v1); }
                else if (act == 2) { v0 = softplus_f(v0); v1 = softplus_f(v1); }
                if (outmode == 0) {
                    *(float2*)(Cf + (size_t)mrow * DIM + ncol) = make_float2(v0, v1);
                } else {
                    *(__half2*)(Ch + (size_t)mrow * DIM + ncol) =
                        __halves2half2(__float2half_rn(v0), __float2half_rn(v1));
                }
            }
        }
    }
}

// ---------------------------------------------------------------------------
// Fused first-layer GEMM: N=4096 over concatenated weights (q1,k1,v,g), GELU
// ---------------------------------------------------------------------------
__global__ __launch_bounds__(256, 2)
void gemm_mma4(const __half* __restrict__ A, const __half* __restrict__ Wcat,
               const float* __restrict__ bq, const float* __restrict__ bk,
               const float* __restrict__ bv, const float* __restrict__ bg,
               __half* __restrict__ dq, __half* __restrict__ dk,
               __half* __restrict__ dv, __half* __restrict__ dg)
{
    extern __shared__ char smem[];
    const uint32_t sb = smem_u32(smem);
    const int t  = threadIdx.x;
    const int m0 = blockIdx.y * 128;
    const int n0 = blockIdx.x * 128;
    const int seg = blockIdx.x >> 3;          // 8 CTAs per 1024-col segment
    const int nloc0 = n0 & 1023;

    const float* bias = (seg == 0) ? bq : (seg == 1) ? bk : (seg == 2) ? bv : bg;
    __half* dst = (seg == 0) ? dq : (seg == 1) ? dk : (seg == 2) ? dv : dg;

    float acc[2][8][4];
#pragma unroll
    for (int im = 0; im < 2; im++)
#pragma unroll
        for (int in = 0; in < 8; in++)
#pragma unroll
            for (int j = 0; j < 4; j++) acc[im][in][j] = 0.0f;

    gemm_core(A, Wcat, sb, t, m0, n0, acc);

    const int lane = t & 31;
    const int w    = t >> 5;
    const int wm   = w & 3;
    const int wn   = w >> 2;
    const int r0 = lane >> 2;
    const int c0 = (lane & 3) * 2;
#pragma unroll
    for (int im = 0; im < 2; im++) {
#pragma unroll
        for (int in = 0; in < 8; in++) {
            const int ncol = nloc0 + wn * 64 + in * 8 + c0;
            const float b0 = __ldg(&bias[ncol]);
            const float b1 = __ldg(&bias[ncol + 1]);
#pragma unroll
            for (int half = 0; half < 2; half++) {
                const int mrow = m0 + wm * 32 + im * 16 + r0 + half * 8;
                float v0 = gelu_f(acc[im][in][half * 2]     + b0);
                float v1 = gelu_f(acc[im][in][half * 2 + 1] + b1);
                *(__half2*)(dst + (size_t)mrow * DIM + ncol) =
                    __halves2half2(__float2half_rn(v0), __float2half_rn(v1));
            }
        }
    }
}

// ---------------------------------------------------------------------------
// Fused second-layer GEMM: N=2048 (q_w2 | k_w2), softplus, fp16 out
// A is selected per segment: hq for seg0, hk for seg1.
// ---------------------------------------------------------------------------
__global__ __launch_bounds__(256, 2)
void gemm_mma2(const __half* __restrict__ Aq, const __half* __restrict__ Ak,
               const __half* __restrict__ W2,
               const float* __restrict__ bq2, const float* __restrict__ bk2,
               __half* __restrict__ dq, __half* __restrict__ dk)
{
    extern __shared__ char smem[];
    const uint32_t sb = smem_u32(smem);
    const int t  = threadIdx.x;
    const int m0 = blockIdx.y * 128;
    const int n0 = blockIdx.x * 128;          // [0, 2048)
    const int seg = blockIdx.x >> 3;          // 0: q, 1: k
    const int nloc0 = n0 & 1023;

    const __half* A = (seg == 0) ? Aq : Ak;
    const float* bias = (seg == 0) ? bq2 : bk2;
    __half* dst = (seg == 0) ? dq : dk;

    float acc[2][8][4];
#pragma unroll
    for (int im = 0; im < 2; im++)
#pragma unroll
        for (int in = 0; in < 8; in++)
#pragma unroll
            for (int j = 0; j < 4; j++) acc[im][in][j] = 0.0f;

    gemm_core(A, W2, sb, t, m0, n0, acc);

    const int lane = t & 31;
    const int w    = t >> 5;
    const int wm   = w & 3;
    const int wn   = w >> 2;
    const int r0 = lane >> 2;
    const int c0 = (lane & 3) * 2;
#pragma unroll
    for (int im = 0; im < 2; im++) {
#pragma unroll
        for (int in = 0; in < 8; in++) {
            const int ncol = nloc0 + wn * 64 + in * 8 + c0;
            const float b0 = __ldg(&bias[ncol]);
            const float b1 = __ldg(&bias[ncol + 1]);
#pragma unroll
            for (int half = 0; half < 2; half++) {
                const int mrow = m0 + wm * 32 + im * 16 + r0 + half * 8;
                float v0 = softplus_f(acc[im][in][half * 2]     + b0);
                float v1 = softplus_f(acc[im][in][half * 2 + 1] + b1);
                *(__half2*)(dst + (size_t)mrow * DIM + ncol) =
                    __halves2half2(__float2half_rn(v0), __float2half_rn(v1));
            }
        }
    }
}

// ---------------------------------------------------------------------------
// Attention pass 1 (partial) — fp16 q/k inputs, fp32 compute
// ---------------------------------------------------------------------------
__global__ __launch_bounds__(512)
void attn_pass1p(const __half* __restrict__ q, const __half* __restrict__ k,
                 float* __restrict__ Ap, float* __restrict__ Zp)
{
    const int bh = blockIdx.x;
    const int ch = blockIdx.y;
    const int b  = bh >> 4;
    const int h  = bh & 15;
    const __half* qb = q + (size_t)b * NTOK * DIM + h * HD;
    const __half* kb = k + (size_t)b * NTOK * DIM + h * HD;

    __shared__ float qs[64][64];
    __shared__ float ks[64][64];
    __shared__ float ksum[64];

    const int t  = threadIdx.x;
    const int n  = t >> 3;
    const int m0 = (t & 7) << 3;
    const int lr = t >> 3;
    const int lc = (t & 7) << 3;

    float acc[8] = {0, 0, 0, 0, 0, 0, 0, 0};
    float zacc = 0.0f;
    const bool zowner = ((t & 7) == 0);

    const int cbeg = ch * (NTOK / NCHUNK);
    const int cend = cbeg + (NTOK / NCHUNK);
    for (int c0 = cbeg; c0 < cend; c0 += 64) {
        const uint4 qr = *(const uint4*)(qb + (size_t)(c0 + lr) * DIM + lc);
        const uint4 kr = *(const uint4*)(kb + (size_t)(c0 + lr) * DIM + lc);
        __syncthreads();
        {
            const __half2* qp = (const __half2*)&qr;
            const __half2* kp = (const __half2*)&kr;
#pragma unroll
            for (int j = 0; j < 4; j++) {
                float2 qf = __half22float2(qp[j]);
                float2 kf = __half22float2(kp[j]);
                qs[lr][lc + 2 * j]     = qf.x;
                qs[lr][lc + 2 * j + 1] = qf.y;
                ks[lr][lc + 2 * j]     = kf.x;
                ks[lr][lc + 2 * j + 1] = kf.y;
            }
        }
        __syncthreads();
        if (t < 64) {
            float s = 0.0f;
#pragma unroll
            for (int m = 0; m < 64; m++) s += ks[t][(m + t) & 63];
            ksum[t] = s;
        }
        __syncthreads();

#pragma unroll 4
        for (int c = 0; c < 64; c++) {
            float qv = qs[c][n];
            float4 k4a = *(const float4*)&ks[c][m0];
            float4 k4b = *(const float4*)&ks[c][m0 + 4];
            acc[0] += qv * k4a.x; acc[1] += qv * k4a.y;
            acc[2] += qv * k4a.z; acc[3] += qv * k4a.w;
            acc[4] += qv * k4b.x; acc[5] += qv * k4b.y;
            acc[6] += qv * k4b.z; acc[7] += qv * k4b.w;
            if (zowner) zacc += qv * ksum[c];
        }
    }

    float* Abh = Ap + ((size_t)ch * 64 + bh) * HD * HD;
#pragma unroll
    for (int j = 0; j < 8; j++)
        Abh[(m0 + j) * HD + n] = acc[j];
    if (zowner)
        Zp[((size_t)ch * 64 + bh) * HD + n] = zacc;
}

__global__ __launch_bounds__(256)
void attn_reduce(const float* __restrict__ Ap, const float* __restrict__ Zp,
                 float* __restrict__ gA, float* __restrict__ gZ)
{
    const int bh = blockIdx.x;
    const int t  = threadIdx.x;
    for (int i = t; i < HD * HD; i += 256) {
        float s = 0.0f;
#pragma unroll
        for (int c = 0; c < NCHUNK; c++)
            s += Ap[((size_t)c * 64 + bh) * HD * HD + i];
        gA[(size_t)bh * HD * HD + i] = s;
    }
    if (t < HD) {
        float s = 0.0f;
#pragma unroll
        for (int c = 0; c < NCHUNK; c++)
            s += Zp[((size_t)c * 64 + bh) * HD + t];
        gZ[bh * HD + t] = 1.0f / (SCALE * s + (float)DIM);
    }
}

// ---------------------------------------------------------------------------
// Attention pass 2 — full grid (64, 64)
// ---------------------------------------------------------------------------
__global__ __launch_bounds__(256)
void attn_pass2(const __half* __restrict__ v, const __half* __restrict__ gg,
                const float* __restrict__ gA, const float* __restrict__ gZ,
                __half* __restrict__ Yh)
{
    const int bh = blockIdx.x;
    const int b  = bh >> 4;
    const int h  = bh & 15;
    const int c0 = blockIdx.y * 64;

    __shared__ float As[HD * HD];
    __shared__ float vs[64][64];
    __shared__ float zs[64];

    const int t = threadIdx.x;

    const float4* Asrc = (const float4*)(gA + (size_t)bh * HD * HD);
#pragma unroll
    for (int i = t; i < HD * HD / 4; i += 256)
        ((float4*)As)[i] = Asrc[i];
    if (t < 64) zs[t] = gZ[bh * HD + t];

    {
        const int lr = t >> 2;
        const int lc = (t & 3) << 4;
        const __half* vrow = v + (size_t)(b * NTOK + c0 + lr) * DIM + h * HD + lc;
        uint4 r0 = *(const uint4*)(vrow);
        uint4 r1 = *(const uint4*)(vrow + 8);
        const __half2* p0 = (const __half2*)&r0;
        const __half2* p1 = (const __half2*)&r1;
#pragma unroll
        for (int j = 0; j < 4; j++) {
            float2 f0 = __half22float2(p0[j]);
            float2 f1 = __half22float2(p1[j]);
            vs[lr][lc + 2 * j]         = f0.x;
            vs[lr][lc + 2 * j + 1]     = f0.y;
            vs[lr][lc + 8 + 2 * j]     = f1.x;
            vs[lr][lc + 8 + 2 * j + 1] = f1.y;
        }
    }
    __syncthreads();

    const int nloc = t & 63;
    const int dgrp = t >> 6;

    for (int d = dgrp; d < 64; d += 4) {
        float accv = 0.0f;
#pragma unroll
        for (int m = 0; m < 64; m++)
            accv += As[m * 64 + nloc] * vs[d][m];
        const int tok = c0 + d;
        float val = (SCALE * accv + vs[d][nloc]) * zs[nloc];
        val *= __half2float(gg[(size_t)(b * NTOK + tok) * DIM + h * HD + nloc]);
        const int row = b * NTOK + h * 256 + (tok >> 4);
        const int col = ((tok & 15) << 6) + nloc;
        Yh[(size_t)row * DIM + col] = __float2half_rn(val);
    }
}

// ---------------------------------------------------------------------------
// Launch — capture-safe fork/join; single-stream main pipeline
// ---------------------------------------------------------------------------
extern "C" void kernel_launch(void* const* d_in, const int* in_sizes, int n_in,
                              void* d_out, int out_size)
{
    const float* x    = (const float*)d_in[0];
    const float* q_w1 = (const float*)d_in[1];
    const float* q_b1 = (const float*)d_in[2];
    const float* q_w2 = (const float*)d_in[3];
    const float* q_b2 = (const float*)d_in[4];
    const float* k_w1 = (const float*)d_in[5];
    const float* k_b1 = (const float*)d_in[6];
    const float* k_w2 = (const float*)d_in[7];
    const float* k_b2 = (const float*)d_in[8];
    const float* v_w  = (const float*)d_in[9];
    const float* v_b  = (const float*)d_in[10];
    const float* g_w  = (const float*)d_in[11];
    const float* g_b  = (const float*)d_in[12];
    const float* p_w  = (const float*)d_in[13];
    const float* p_b  = (const float*)d_in[14];
    float* out = (float*)d_out;

    __half *xh, *hqh, *hkh, *yh, *wcat, *w2, *wp, *qb, *kb, *vb, *gb;
    float *Ab, *zb, *Apb, *zpb;
    cudaGetSymbolAddress((void**)&xh,   g_x_h);
    cudaGetSymbolAddress((void**)&hqh,  g_hq_h);
    cudaGetSymbolAddress((void**)&hkh,  g_hk_h);
    cudaGetSymbolAddress((void**)&yh,   g_y_h);
    cudaGetSymbolAddress((void**)&wcat, g_wcat);
    cudaGetSymbolAddress((void**)&w2,   g_w2);
    cudaGetSymbolAddress((void**)&wp,   g_wp);
    cudaGetSymbolAddress((void**)&qb,   g_q);
    cudaGetSymbolAddress((void**)&kb,   g_k);
    cudaGetSymbolAddress((void**)&vb,   g_v);
    cudaGetSymbolAddress((void**)&gb,   g_g);
    cudaGetSymbolAddress((void**)&Ab,   g_A);
    cudaGetSymbolAddress((void**)&zb,   g_z);
    cudaGetSymbolAddress((void**)&Apb,  g_Ap);
    cudaGetSymbolAddress((void**)&zpb,  g_zp);

    static bool init_done = false;
    static cudaStream_t s1, s2, s3;
    static cudaEvent_t ev_fork, ev_c1, ev_c2, ev_c3, ev_w2, ev_pw;
    if (!init_done) {
        cudaFuncSetAttribute(gemm_mma,  cudaFuncAttributeMaxDynamicSharedMemorySize, GSMEM_TOTAL);
        cudaFuncSetAttribute(gemm_mma2, cudaFuncAttributeMaxDynamicSharedMemorySize, GSMEM_TOTAL);
        cudaFuncSetAttribute(gemm_mma4, cudaFuncAttributeMaxDynamicSharedMemorySize, GSMEM_TOTAL);
        cudaStreamCreateWithFlags(&s1, cudaStreamNonBlocking);
        cudaStreamCreateWithFlags(&s2, cudaStreamNonBlocking);
        cudaStreamCreateWithFlags(&s3, cudaStreamNonBlocking);
        cudaEventCreateWithFlags(&ev_fork, cudaEventDisableTiming);
        cudaEventCreateWithFlags(&ev_c1,   cudaEventDisableTiming);
        cudaEventCreateWithFlags(&ev_c2,   cudaEventDisableTiming);
        cudaEventCreateWithFlags(&ev_c3,   cudaEventDisableTiming);
        cudaEventCreateWithFlags(&ev_w2,   cudaEventDisableTiming);
        cudaEventCreateWithFlags(&ev_pw,   cudaEventDisableTiming);
        init_done = true;
    }

    const int WSZ = DIM * DIM;
    const int W8  = WSZ / 8;

    // === fork: side streams join capture first ===
    cudaEventRecord(ev_fork, 0);
    cudaStreamWaitEvent(s1, ev_fork, 0);
    cudaStreamWaitEvent(s2, ev_fork, 0);
    cudaStreamWaitEvent(s3, ev_fork, 0);

    // --- conversions ---
    // s1: q_w1 (seg0), g_w (seg3)
    conv_f2h_w<<<592, 256, 0, s1>>>((const float4*)q_w1, (uint4*)(wcat), W8);
    conv_f2h_w<<<592, 256, 0, s1>>>((const float4*)g_w,  (uint4*)(wcat + 3 * (size_t)WSZ), W8);
    cudaEventRecord(ev_c1, s1);
    // s2: k_w1 (seg1), then q_w2 + k_w2 into w2
    conv_f2h_w<<<592, 256, 0, s2>>>((const float4*)k_w1, (uint4*)(wcat + 1 * (size_t)WSZ), W8);
    cudaEventRecord(ev_c2, s2);
    conv_f2h_w<<<592, 256, 0, s2>>>((const float4*)q_w2, (uint4*)(w2), W8);
    conv_f2h_w<<<592, 256, 0, s2>>>((const float4*)k_w2, (uint4*)(w2 + (size_t)WSZ), W8);
    cudaEventRecord(ev_w2, s2);
    // s3: v_w (seg2), then p_w
    conv_f2h_w<<<592, 256, 0, s3>>>((const float4*)v_w,  (uint4*)(wcat + 2 * (size_t)WSZ), W8);
    cudaEventRecord(ev_c3, s3);
    conv_f2h_w<<<592, 256, 0, s3>>>((const float4*)p_w,  (uint4*)(wp), W8);
    cudaEventRecord(ev_pw, s3);
    // s0: x (critical head)
    conv_f2h_w<<<2048, 256>>>((const float4*)x, (uint4*)xh, MROWS * DIM / 8);

    // --- G1: fused first layer (q1,k1,v,g) ---
    cudaStreamWaitEvent(0, ev_c1, 0);
    cudaStreamWaitEvent(0, ev_c2, 0);
    cudaStreamWaitEvent(0, ev_c3, 0);
    gemm_mma4<<<dim3(4 * DIM / 128, MROWS / 128), 256, GSMEM_TOTAL>>>(
        xh, wcat, q_b1, k_b1, v_b, g_b, hqh, hkh, vb, gb);

    // --- G2: fused second layer (q2 | k2) ---
    cudaStreamWaitEvent(0, ev_w2, 0);
    gemm_mma2<<<dim3(2 * DIM / 128, MROWS / 128), 256, GSMEM_TOTAL>>>(
        hqh, hkh, w2, q_b2, k_b2, qb, kb);

    // --- attention ---
    attn_pass1p<<<dim3(BATCH * NHEAD, NCHUNK), 512>>>(qb, kb, Apb, zpb);
    attn_reduce<<<BATCH * NHEAD, 256>>>(Apb, zpb, Ab, zb);
    attn_pass2<<<dim3(BATCH * NHEAD, NTOK / 64), 256>>>(vb, gb, Ab, zb, yh);

    // --- final projection ---
    cudaStreamWaitEvent(0, ev_pw, 0);
    gemm_mma<<<dim3(DIM / 128, MROWS / 128), 256, GSMEM_TOTAL>>>(
        yh, wp, p_b, 0, 0, out, nullptr);
}

// round 14
// speedup vs baseline: 1.0244x; 1.0159x over previous
#include <cuda_runtime.h>
#include <cuda_fp16.h>
#include <math.h>
#include <stdint.h>

// Problem constants
#define BATCH 4
#define NTOK 4096
#define DIM 1024
#define NHEAD 16
#define HD 64
#define MROWS (BATCH * NTOK)          // 16384
#define SCALE 0.125f                  // HD^-0.5
#define NCHUNK 4

// ---------------------------------------------------------------------------
// Scratch buffers
// ---------------------------------------------------------------------------
__device__ __half g_x_h [MROWS * DIM];
__device__ __half g_hq_h[MROWS * DIM];
__device__ __half g_hk_h[MROWS * DIM];
__device__ __half g_y_h [MROWS * DIM];
__device__ __half g_q [MROWS * DIM];
__device__ __half g_k [MROWS * DIM];
__device__ __half g_v [MROWS * DIM];
__device__ __half g_g [MROWS * DIM];
__device__ float g_A [BATCH * NHEAD * HD * HD];
__device__ float g_z [BATCH * NHEAD * HD];
__device__ float g_Ap[NCHUNK * BATCH * NHEAD * HD * HD];
__device__ float g_zp[NCHUNK * BATCH * NHEAD * HD];
__device__ __half g_w_h [7 * DIM * DIM];   // q1|q2|k1|k2|v|g|p

// ---------------------------------------------------------------------------
// PTX helpers (sm_80+ portable)
// ---------------------------------------------------------------------------
__device__ __forceinline__ uint32_t smem_u32(const void* p) {
    uint32_t a;
    asm("{ .reg .u64 t; cvta.to.shared.u64 t, %1; cvt.u32.u64 %0, t; }" : "=r"(a) : "l"(p));
    return a;
}
#define SWZ(o) ((o) ^ (((o) >> 3) & 0x70))

__device__ __forceinline__ void cp16(uint32_t saddr, const void* g) {
    asm volatile("cp.async.cg.shared.global [%0], [%1], 16;" :: "r"(saddr), "l"(g));
}
#define CP_COMMIT() asm volatile("cp.async.commit_group;" ::: "memory")
#define CP_WAIT(N)  asm volatile("cp.async.wait_group %0;" :: "n"(N) : "memory")

#define LDSM4(r, a) \
    asm volatile("ldmatrix.sync.aligned.m8n8.x4.shared.b16 {%0,%1,%2,%3}, [%4];" \
        : "=r"((r)[0]), "=r"((r)[1]), "=r"((r)[2]), "=r"((r)[3]) : "r"(a))

#define MMA16816F(c, a, b) \
    asm volatile("mma.sync.aligned.m16n8k16.row.col.f32.f16.f16.f32 " \
        "{%0,%1,%2,%3}, {%4,%5,%6,%7}, {%8,%9}, {%0,%1,%2,%3};" \
        : "+f"((c)[0]), "+f"((c)[1]), "+f"((c)[2]), "+f"((c)[3]) \
        : "r"((a)[0]), "r"((a)[1]), "r"((a)[2]), "r"((a)[3]), \
          "r"((b)[0]), "r"((b)[1]))

// ---------------------------------------------------------------------------
// Activations
// ---------------------------------------------------------------------------
__device__ __forceinline__ float gelu_f(float x) {
    return 0.5f * x * (1.0f + erff(x * 0.70710678118654752440f));
}
__device__ __forceinline__ float softplus_f(float x) {
    return fmaxf(x, 0.0f) + log1pf(__expf(-fabsf(x)));
}
__device__ __forceinline__ uint32_t pack2h(float a, float b) {
    __half2 h = __halves2half2(__float2half_rn(a), __float2half_rn(b));
    return *(uint32_t*)&h;
}

// ---------------------------------------------------------------------------
// fp32 -> fp16 convert, 8 elems/thread/iter
// ---------------------------------------------------------------------------
__global__ __launch_bounds__(256)
void conv_f2h_w(const float4* __restrict__ src, uint4* __restrict__ dst, int n8)
{
    const int stride = gridDim.x * blockDim.x;
    for (int i = blockIdx.x * blockDim.x + threadIdx.x; i < n8; i += stride) {
        float4 a = src[2 * i];
        float4 b = src[2 * i + 1];
        uint4 d;
        d.x = pack2h(a.x, a.y);
        d.y = pack2h(a.z, a.w);
        d.z = pack2h(b.x, b.y);
        d.w = pack2h(b.z, b.w);
        dst[i] = d;
    }
}

// ---------------------------------------------------------------------------
// HMMA fp16 GEMM core (champion, unchanged since R8)
// ---------------------------------------------------------------------------
#define TILE_B 16384
#define STAGE_B (2 * TILE_B)
#define NSTAGE 3
#define GSMEM_TOTAL (NSTAGE * STAGE_B)  // 98304

__global__ __launch_bounds__(256, 2)
void gemm_mma(const __half* __restrict__ A, const __half* __restrict__ Wh,
              const float* __restrict__ bias, int act, int outmode,
              float* __restrict__ Cf, __half* __restrict__ Ch)
{
    extern __shared__ char smem[];
    const uint32_t sb = smem_u32(smem);
    const int t    = threadIdx.x;
    const int lane = t & 31;
    const int w    = t >> 5;
    const int wm   = w & 3;
    const int wn   = w >> 2;
    const int m0   = blockIdx.y * 128;
    const int n0   = blockIdx.x * 128;

    const int lrow = t >> 3;
    const int lu   = t & 7;

    auto issue = [&](int stage, int kc) {
        const uint32_t sbase = sb + stage * STAGE_B;
        const int kbase = kc * 64 + lu * 8;
#pragma unroll
        for (int i = 0; i < 4; i++) {
            const int row = lrow + i * 32;
            const uint32_t soff = SWZ((uint32_t)(row * 128 + lu * 16));
            cp16(sbase + soff,          A  + (size_t)(m0 + row) * DIM + kbase);
            cp16(sbase + TILE_B + soff, Wh + (size_t)(n0 + row) * DIM + kbase);
        }
        CP_COMMIT();
    };

    issue(0, 0);
    issue(1, 1);

    float acc[2][8][4];
#pragma unroll
    for (int im = 0; im < 2; im++)
#pragma unroll
        for (int in = 0; in < 8; in++)
#pragma unroll
            for (int j = 0; j < 4; j++) acc[im][in][j] = 0.0f;

    const int g  = lane >> 3;
    const int rr = lane & 7;

    for (int kc = 0; kc < 16; kc++) {
        if (kc == 15) { CP_WAIT(0); } else { CP_WAIT(1); }
        __syncthreads();
        if (kc + 2 < 16) issue((kc + 2) % NSTAGE, kc + 2);

        const uint32_t st = sb + (kc % NSTAGE) * STAGE_B;
#pragma unroll
        for (int kk = 0; kk < 4; kk++) {
            const int ku = kk * 2 + (g >> 1);
            uint32_t ah[2][4];
#pragma unroll
            for (int im = 0; im < 2; im++) {
                const int row = wm * 32 + im * 16 + (g & 1) * 8 + rr;
                const uint32_t off = SWZ((uint32_t)(row * 128 + ku * 16));
                LDSM4(ah[im], st + off);
            }
            uint32_t bh[8][2];
#pragma unroll
            for (int in2 = 0; in2 < 4; in2++) {
                const int row = wn * 64 + in2 * 16 + (g & 1) * 8 + rr;
                const uint32_t off = SWZ((uint32_t)(row * 128 + ku * 16));
                uint32_t qh[4];
                LDSM4(qh, st + TILE_B + off);
                bh[2 * in2][0] = qh[0]; bh[2 * in2][1] = qh[2];
                bh[2 * in2 + 1][0] = qh[1]; bh[2 * in2 + 1][1] = qh[3];
            }
#pragma unroll
            for (int im = 0; im < 2; im++)
#pragma unroll
                for (int in = 0; in < 8; in++)
                    MMA16816F(acc[im][in], ah[im], bh[in]);
        }
    }

    const int r0 = lane >> 2;
    const int c0 = (lane & 3) * 2;
#pragma unroll
    for (int im = 0; im < 2; im++) {
#pragma unroll
        for (int in = 0; in < 8; in++) {
            const int ncol = n0 + wn * 64 + in * 8 + c0;
            const float b0 = __ldg(&bias[ncol]);
            const float b1 = __ldg(&bias[ncol + 1]);
#pragma unroll
            for (int half = 0; half < 2; half++) {
                const int mrow = m0 + wm * 32 + im * 16 + r0 + half * 8;
                float v0 = acc[im][in][half * 2]     + b0;
                float v1 = acc[im][in][half * 2 + 1] + b1;
                if (act == 1)      { v0 = gelu_f(v0);     v1 = gelu_f(v1); }
                else if (act == 2) { v0 = softplus_f(v0); v1 = softplus_f(v1); }
                if (outmode == 0) {
                    *(float2*)(Cf + (size_t)mrow * DIM + ncol) = make_float2(v0, v1);
                } else {
                    *(__half2*)(Ch + (size_t)mrow * DIM + ncol) =
                        __halves2half2(__float2half_rn(v0), __float2half_rn(v1));
                }
            }
        }
    }
}

// ---------------------------------------------------------------------------
// Attention pass 1 (partial) — fp16 q/k inputs, fp32 compute
// ---------------------------------------------------------------------------
__global__ __launch_bounds__(512)
void attn_pass1p(const __half* __restrict__ q, const __half* __restrict__ k,
                 float* __restrict__ Ap, float* __restrict__ Zp)
{
    const int bh = blockIdx.x;
    const int ch = blockIdx.y;
    const int b  = bh >> 4;
    const int h  = bh & 15;
    const __half* qb = q + (size_t)b * NTOK * DIM + h * HD;
    const __half* kb = k + (size_t)b * NTOK * DIM + h * HD;

    __shared__ float qs[64][64];
    __shared__ float ks[64][64];
    __shared__ float ksum[64];

    const int t  = threadIdx.x;
    const int n  = t >> 3;
    const int m0 = (t & 7) << 3;
    const int lr = t >> 3;
    const int lc = (t & 7) << 3;

    float acc[8] = {0, 0, 0, 0, 0, 0, 0, 0};
    float zacc = 0.0f;
    const bool zowner = ((t & 7) == 0);

    const int cbeg = ch * (NTOK / NCHUNK);
    const int cend = cbeg + (NTOK / NCHUNK);
    for (int c0 = cbeg; c0 < cend; c0 += 64) {
        const uint4 qr = *(const uint4*)(qb + (size_t)(c0 + lr) * DIM + lc);
        const uint4 kr = *(const uint4*)(kb + (size_t)(c0 + lr) * DIM + lc);
        __syncthreads();
        {
            const __half2* qp = (const __half2*)&qr;
            const __half2* kp = (const __half2*)&kr;
#pragma unroll
            for (int j = 0; j < 4; j++) {
                float2 qf = __half22float2(qp[j]);
                float2 kf = __half22float2(kp[j]);
                qs[lr][lc + 2 * j]     = qf.x;
                qs[lr][lc + 2 * j + 1] = qf.y;
                ks[lr][lc + 2 * j]     = kf.x;
                ks[lr][lc + 2 * j + 1] = kf.y;
            }
        }
        __syncthreads();
        if (t < 64) {
            float s = 0.0f;
#pragma unroll
            for (int m = 0; m < 64; m++) s += ks[t][(m + t) & 63];
            ksum[t] = s;
        }
        __syncthreads();

#pragma unroll 4
        for (int c = 0; c < 64; c++) {
            float qv = qs[c][n];
            float4 k4a = *(const float4*)&ks[c][m0];
            float4 k4b = *(const float4*)&ks[c][m0 + 4];
            acc[0] += qv * k4a.x; acc[1] += qv * k4a.y;
            acc[2] += qv * k4a.z; acc[3] += qv * k4a.w;
            acc[4] += qv * k4b.x; acc[5] += qv * k4b.y;
            acc[6] += qv * k4b.z; acc[7] += qv * k4b.w;
            if (zowner) zacc += qv * ksum[c];
        }
    }

    float* Abh = Ap + ((size_t)ch * 64 + bh) * HD * HD;
#pragma unroll
    for (int j = 0; j < 8; j++)
        Abh[(m0 + j) * HD + n] = acc[j];
    if (zowner)
        Zp[((size_t)ch * 64 + bh) * HD + n] = zacc;
}

__global__ __launch_bounds__(256)
void attn_reduce(const float* __restrict__ Ap, const float* __restrict__ Zp,
                 float* __restrict__ gA, float* __restrict__ gZ)
{
    const int bh = blockIdx.x;
    const int t  = threadIdx.x;
    for (int i = t; i < HD * HD; i += 256) {
        float s = 0.0f;
#pragma unroll
        for (int c = 0; c < NCHUNK; c++)
            s += Ap[((size_t)c * 64 + bh) * HD * HD + i];
        gA[(size_t)bh * HD * HD + i] = s;
    }
    if (t < HD) {
        float s = 0.0f;
#pragma unroll
        for (int c = 0; c < NCHUNK; c++)
            s += Zp[((size_t)c * 64 + bh) * HD + t];
        gZ[bh * HD + t] = 1.0f / (SCALE * s + (float)DIM);
    }
}

// ---------------------------------------------------------------------------
// Attention pass 2 — fp16 v/g inputs, fp32 compute, fp16 scrambled output
// ---------------------------------------------------------------------------
__global__ __launch_bounds__(256)
void attn_pass2(const __half* __restrict__ v, const __half* __restrict__ gg,
                const float* __restrict__ gA, const float* __restrict__ gZ,
                __half* __restrict__ Yh)
{
    const int bh = blockIdx.x;
    const int b  = bh >> 4;
    const int h  = bh & 15;
    const int c0 = blockIdx.y * 64;

    __shared__ float As[HD * HD];
    __shared__ float vs[64][64];
    __shared__ float zs[64];

    const int t = threadIdx.x;

    const float4* Asrc = (const float4*)(gA + (size_t)bh * HD * HD);
#pragma unroll
    for (int i = t; i < HD * HD / 4; i += 256)
        ((float4*)As)[i] = Asrc[i];
    if (t < 64) zs[t] = gZ[bh * HD + t];

    {
        const int lr = t >> 2;
        const int lc = (t & 3) << 4;
        const __half* vrow = v + (size_t)(b * NTOK + c0 + lr) * DIM + h * HD + lc;
        uint4 r0 = *(const uint4*)(vrow);
        uint4 r1 = *(const uint4*)(vrow + 8);
        const __half2* p0 = (const __half2*)&r0;
        const __half2* p1 = (const __half2*)&r1;
#pragma unroll
        for (int j = 0; j < 4; j++) {
            float2 f0 = __half22float2(p0[j]);
            float2 f1 = __half22float2(p1[j]);
            vs[lr][lc + 2 * j]         = f0.x;
            vs[lr][lc + 2 * j + 1]     = f0.y;
            vs[lr][lc + 8 + 2 * j]     = f1.x;
            vs[lr][lc + 8 + 2 * j + 1] = f1.y;
        }
    }
    __syncthreads();

    const int nloc = t & 63;
    const int dgrp = t >> 6;

    for (int d = dgrp; d < 64; d += 4) {
        float accv = 0.0f;
#pragma unroll
        for (int m = 0; m < 64; m++)
            accv += As[m * 64 + nloc] * vs[d][m];
        const int tok = c0 + d;
        float val = (SCALE * accv + vs[d][nloc]) * zs[nloc];
        val *= __half2float(gg[(size_t)(b * NTOK + tok) * DIM + h * HD + nloc]);
        const int row = b * NTOK + h * 256 + (tok >> 4);
        const int col = ((tok & 15) << 6) + nloc;
        Yh[(size_t)row * DIM + col] = __float2half_rn(val);
    }
}

// ---------------------------------------------------------------------------
// Launch — q/k chain prioritized; pass1 hidden under v/g GEMMs
// ---------------------------------------------------------------------------
extern "C" void kernel_launch(void* const* d_in, const int* in_sizes, int n_in,
                              void* d_out, int out_size)
{
    const float* x    = (const float*)d_in[0];
    const float* q_w1 = (const float*)d_in[1];
    const float* q_b1 = (const float*)d_in[2];
    const float* q_w2 = (const float*)d_in[3];
    const float* q_b2 = (const float*)d_in[4];
    const float* k_w1 = (const float*)d_in[5];
    const float* k_b1 = (const float*)d_in[6];
    const float* k_w2 = (const float*)d_in[7];
    const float* k_b2 = (const float*)d_in[8];
    const float* v_w  = (const float*)d_in[9];
    const float* v_b  = (const float*)d_in[10];
    const float* g_w  = (const float*)d_in[11];
    const float* g_b  = (const float*)d_in[12];
    const float* p_w  = (const float*)d_in[13];
    const float* p_b  = (const float*)d_in[14];
    float* out = (float*)d_out;

    __half *xh, *hqh, *hkh, *yh, *wh, *qb, *kb, *vb, *gb;
    float *Ab, *zb, *Apb, *zpb;
    cudaGetSymbolAddress((void**)&xh,  g_x_h);
    cudaGetSymbolAddress((void**)&hqh, g_hq_h);
    cudaGetSymbolAddress((void**)&hkh, g_hk_h);
    cudaGetSymbolAddress((void**)&yh,  g_y_h);
    cudaGetSymbolAddress((void**)&wh,  g_w_h);
    cudaGetSymbolAddress((void**)&qb,  g_q);
    cudaGetSymbolAddress((void**)&kb,  g_k);
    cudaGetSymbolAddress((void**)&vb,  g_v);
    cudaGetSymbolAddress((void**)&gb,  g_g);
    cudaGetSymbolAddress((void**)&Ab,  g_A);
    cudaGetSymbolAddress((void**)&zb,  g_z);
    cudaGetSymbolAddress((void**)&Apb, g_Ap);
    cudaGetSymbolAddress((void**)&zpb, g_zp);

    static bool init_done = false;
    static cudaStream_t s1, s2, s3;
    static cudaEvent_t ev_fork, ev_x, ev_qw, ev_k2, ev_v, ev_g, ev_pw;
    if (!init_done) {
        cudaFuncSetAttribute(gemm_mma, cudaFuncAttributeMaxDynamicSharedMemorySize, GSMEM_TOTAL);
        cudaStreamCreateWithFlags(&s1, cudaStreamNonBlocking);
        cudaStreamCreateWithFlags(&s2, cudaStreamNonBlocking);
        cudaStreamCreateWithFlags(&s3, cudaStreamNonBlocking);
        cudaEventCreateWithFlags(&ev_fork, cudaEventDisableTiming);
        cudaEventCreateWithFlags(&ev_x,    cudaEventDisableTiming);
        cudaEventCreateWithFlags(&ev_qw,   cudaEventDisableTiming);
        cudaEventCreateWithFlags(&ev_k2,   cudaEventDisableTiming);
        cudaEventCreateWithFlags(&ev_v,    cudaEventDisableTiming);
        cudaEventCreateWithFlags(&ev_g,    cudaEventDisableTiming);
        cudaEventCreateWithFlags(&ev_pw,   cudaEventDisableTiming);
        init_done = true;
    }

    const int WSZ = DIM * DIM;
    const int W8  = WSZ / 8;
#define WH(i) (wh + (size_t)(i) * WSZ)

    dim3 ggrid(DIM / 128, MROWS / 128);   // (8, 128)

    // === fork: side streams join capture first ===
    cudaEventRecord(ev_fork, 0);
    cudaStreamWaitEvent(s1, ev_fork, 0);
    cudaStreamWaitEvent(s2, ev_fork, 0);
    cudaStreamWaitEvent(s3, ev_fork, 0);

    // --- weight conversions on side streams ---
    // s1: k weights (s1 runs the k GEMM chain)
    conv_f2h_w<<<592, 256, 0, s1>>>((const float4*)k_w1, (uint4*)WH(2), W8);
    conv_f2h_w<<<592, 256, 0, s1>>>((const float4*)k_w2, (uint4*)WH(3), W8);
    // s2: q weights (feed s0's q chain), then v weight
    conv_f2h_w<<<592, 256, 0, s2>>>((const float4*)q_w1, (uint4*)WH(0), W8);
    conv_f2h_w<<<592, 256, 0, s2>>>((const float4*)q_w2, (uint4*)WH(1), W8);
    cudaEventRecord(ev_qw, s2);
    conv_f2h_w<<<592, 256, 0, s2>>>((const float4*)v_w,  (uint4*)WH(4), W8);
    // s3: g weight, then p weight
    conv_f2h_w<<<592, 256, 0, s3>>>((const float4*)g_w,  (uint4*)WH(5), W8);
    conv_f2h_w<<<592, 256, 0, s3>>>((const float4*)p_w,  (uint4*)WH(6), W8);
    cudaEventRecord(ev_pw, s3);

    // s0: x convert (critical head)
    conv_f2h_w<<<2048, 256>>>((const float4*)x, (uint4*)xh, MROWS * DIM / 8);
    cudaEventRecord(ev_x, 0);

    // --- q/k chains first (priority by enqueue order) ---
    cudaStreamWaitEvent(0, ev_qw, 0);
    gemm_mma<<<ggrid, 256, GSMEM_TOTAL>>>(xh, WH(0), q_b1, 1, 1, nullptr, hqh);
    cudaStreamWaitEvent(s1, ev_x, 0);
    gemm_mma<<<ggrid, 256, GSMEM_TOTAL, s1>>>(xh, WH(2), k_b1, 1, 1, nullptr, hkh);
    gemm_mma<<<ggrid, 256, GSMEM_TOTAL>>>(hqh, WH(1), q_b2, 2, 1, nullptr, qb);
    gemm_mma<<<ggrid, 256, GSMEM_TOTAL, s1>>>(hkh, WH(3), k_b2, 2, 1, nullptr, kb);
    cudaEventRecord(ev_k2, s1);

    // --- v, g GEMMs trail (overlap with attention pass 1) ---
    cudaStreamWaitEvent(s2, ev_x, 0);
    gemm_mma<<<ggrid, 256, GSMEM_TOTAL, s2>>>(xh, WH(4), v_b, 1, 1, nullptr, vb);
    cudaEventRecord(ev_v, s2);
    cudaStreamWaitEvent(s3, ev_x, 0);
    gemm_mma<<<ggrid, 256, GSMEM_TOTAL, s3>>>(xh, WH(5), g_b, 1, 1, nullptr, gb);
    cudaEventRecord(ev_g, s3);

    // --- attention pass 1 + reduce (s0) — overlaps v/g GEMMs ---
    cudaStreamWaitEvent(0, ev_k2, 0);
    attn_pass1p<<<dim3(BATCH * NHEAD, NCHUNK), 512>>>(qb, kb, Apb, zpb);
    attn_reduce<<<BATCH * NHEAD, 256>>>(Apb, zpb, Ab, zb);

    // --- pass 2 + final projection ---
    cudaStreamWaitEvent(0, ev_v, 0);
    cudaStreamWaitEvent(0, ev_g, 0);
    attn_pass2<<<dim3(BATCH * NHEAD, NTOK / 64), 256>>>(vb, gb, Ab, zb, yh);

    cudaStreamWaitEvent(0, ev_pw, 0);
    gemm_mma<<<ggrid, 256, GSMEM_TOTAL>>>(yh, WH(6), p_b, 0, 0, out, nullptr);
}

// round 15
// speedup vs baseline: 1.5918x; 1.5539x over previous
#include <cuda_runtime.h>
#include <cuda_fp16.h>
#include <math.h>
#include <stdint.h>

// Problem constants
#define BATCH 4
#define NTOK 4096
#define DIM 1024
#define NHEAD 16
#define HD 64
#define MROWS (BATCH * NTOK)          // 16384
#define SCALE 0.125f                  // HD^-0.5
#define NCHUNK 4

// ---------------------------------------------------------------------------
// Scratch buffers
// ---------------------------------------------------------------------------
__device__ __half g_x_h [MROWS * DIM];
__device__ __half g_hq_h[MROWS * DIM];
__device__ __half g_hk_h[MROWS * DIM];
__device__ __half g_y_h [MROWS * DIM];
__device__ __half g_q [MROWS * DIM];
__device__ __half g_k [MROWS * DIM];
__device__ __half g_v [MROWS * DIM];
__device__ __half g_g [MROWS * DIM];
__device__ __half g_A_h[BATCH * NHEAD * HD * HD];   // reduced A, fp16 [n][m]
__device__ float g_z [BATCH * NHEAD * HD];
__device__ float g_Ap[NCHUNK * BATCH * NHEAD * HD * HD];  // partials [n][m]
__device__ __half g_w_h [7 * DIM * DIM];   // q1|q2|k1|k2|v|g|p

// ---------------------------------------------------------------------------
// PTX helpers (sm_80+ portable)
// ---------------------------------------------------------------------------
__device__ __forceinline__ uint32_t smem_u32(const void* p) {
    uint32_t a;
    asm("{ .reg .u64 t; cvta.to.shared.u64 t, %1; cvt.u32.u64 %0, t; }" : "=r"(a) : "l"(p));
    return a;
}
#define SWZ(o) ((o) ^ (((o) >> 3) & 0x70))

__device__ __forceinline__ void cp16(uint32_t saddr, const void* g) {
    asm volatile("cp.async.cg.shared.global [%0], [%1], 16;" :: "r"(saddr), "l"(g));
}
#define CP_COMMIT() asm volatile("cp.async.commit_group;" ::: "memory")
#define CP_WAIT(N)  asm volatile("cp.async.wait_group %0;" :: "n"(N) : "memory")

#define LDSM4(r, a) \
    asm volatile("ldmatrix.sync.aligned.m8n8.x4.shared.b16 {%0,%1,%2,%3}, [%4];" \
        : "=r"((r)[0]), "=r"((r)[1]), "=r"((r)[2]), "=r"((r)[3]) : "r"(a))

#define LDSM4T(r, a) \
    asm volatile("ldmatrix.sync.aligned.m8n8.x4.trans.shared.b16 {%0,%1,%2,%3}, [%4];" \
        : "=r"((r)[0]), "=r"((r)[1]), "=r"((r)[2]), "=r"((r)[3]) : "r"(a))

#define MMA16816F(c, a, b) \
    asm volatile("mma.sync.aligned.m16n8k16.row.col.f32.f16.f16.f32 " \
        "{%0,%1,%2,%3}, {%4,%5,%6,%7}, {%8,%9}, {%0,%1,%2,%3};" \
        : "+f"((c)[0]), "+f"((c)[1]), "+f"((c)[2]), "+f"((c)[3]) \
        : "r"((a)[0]), "r"((a)[1]), "r"((a)[2]), "r"((a)[3]), \
          "r"((b)[0]), "r"((b)[1]))

// ---------------------------------------------------------------------------
// Activations
// ---------------------------------------------------------------------------
__device__ __forceinline__ float gelu_f(float x) {
    return 0.5f * x * (1.0f + erff(x * 0.70710678118654752440f));
}
__device__ __forceinline__ float softplus_f(float x) {
    return fmaxf(x, 0.0f) + log1pf(__expf(-fabsf(x)));
}
__device__ __forceinline__ uint32_t pack2h(float a, float b) {
    __half2 h = __halves2half2(__float2half_rn(a), __float2half_rn(b));
    return *(uint32_t*)&h;
}

// ---------------------------------------------------------------------------
// fp32 -> fp16 convert, 8 elems/thread/iter
// ---------------------------------------------------------------------------
__global__ __launch_bounds__(256)
void conv_f2h_w(const float4* __restrict__ src, uint4* __restrict__ dst, int n8)
{
    const int stride = gridDim.x * blockDim.x;
    for (int i = blockIdx.x * blockDim.x + threadIdx.x; i < n8; i += stride) {
        float4 a = src[2 * i];
        float4 b = src[2 * i + 1];
        uint4 d;
        d.x = pack2h(a.x, a.y);
        d.y = pack2h(a.z, a.w);
        d.z = pack2h(b.x, b.y);
        d.w = pack2h(b.z, b.w);
        dst[i] = d;
    }
}

// ---------------------------------------------------------------------------
// HMMA fp16 GEMM (champion core, unchanged since R8)
// ---------------------------------------------------------------------------
#define TILE_B 16384
#define STAGE_B (2 * TILE_B)
#define NSTAGE 3
#define GSMEM_TOTAL (NSTAGE * STAGE_B)  // 98304

__global__ __launch_bounds__(256, 2)
void gemm_mma(const __half* __restrict__ A, const __half* __restrict__ Wh,
              const float* __restrict__ bias, int act, int outmode,
              float* __restrict__ Cf, __half* __restrict__ Ch)
{
    extern __shared__ char smem[];
    const uint32_t sb = smem_u32(smem);
    const int t    = threadIdx.x;
    const int lane = t & 31;
    const int w    = t >> 5;
    const int wm   = w & 3;
    const int wn   = w >> 2;
    const int m0   = blockIdx.y * 128;
    const int n0   = blockIdx.x * 128;

    const int lrow = t >> 3;
    const int lu   = t & 7;

    auto issue = [&](int stage, int kc) {
        const uint32_t sbase = sb + stage * STAGE_B;
        const int kbase = kc * 64 + lu * 8;
#pragma unroll
        for (int i = 0; i < 4; i++) {
            const int row = lrow + i * 32;
            const uint32_t soff = SWZ((uint32_t)(row * 128 + lu * 16));
            cp16(sbase + soff,          A  + (size_t)(m0 + row) * DIM + kbase);
            cp16(sbase + TILE_B + soff, Wh + (size_t)(n0 + row) * DIM + kbase);
        }
        CP_COMMIT();
    };

    issue(0, 0);
    issue(1, 1);

    float acc[2][8][4];
#pragma unroll
    for (int im = 0; im < 2; im++)
#pragma unroll
        for (int in = 0; in < 8; in++)
#pragma unroll
            for (int j = 0; j < 4; j++) acc[im][in][j] = 0.0f;

    const int g  = lane >> 3;
    const int rr = lane & 7;

    for (int kc = 0; kc < 16; kc++) {
        if (kc == 15) { CP_WAIT(0); } else { CP_WAIT(1); }
        __syncthreads();
        if (kc + 2 < 16) issue((kc + 2) % NSTAGE, kc + 2);

        const uint32_t st = sb + (kc % NSTAGE) * STAGE_B;
#pragma unroll
        for (int kk = 0; kk < 4; kk++) {
            const int ku = kk * 2 + (g >> 1);
            uint32_t ah[2][4];
#pragma unroll
            for (int im = 0; im < 2; im++) {
                const int row = wm * 32 + im * 16 + (g & 1) * 8 + rr;
                const uint32_t off = SWZ((uint32_t)(row * 128 + ku * 16));
                LDSM4(ah[im], st + off);
            }
            uint32_t bh[8][2];
#pragma unroll
            for (int in2 = 0; in2 < 4; in2++) {
                const int row = wn * 64 + in2 * 16 + (g & 1) * 8 + rr;
                const uint32_t off = SWZ((uint32_t)(row * 128 + ku * 16));
                uint32_t qh[4];
                LDSM4(qh, st + TILE_B + off);
                bh[2 * in2][0] = qh[0]; bh[2 * in2][1] = qh[2];
                bh[2 * in2 + 1][0] = qh[1]; bh[2 * in2 + 1][1] = qh[3];
            }
#pragma unroll
            for (int im = 0; im < 2; im++)
#pragma unroll
                for (int in = 0; in < 8; in++)
                    MMA16816F(acc[im][in], ah[im], bh[in]);
        }
    }

    const int r0 = lane >> 2;
    const int c0 = (lane & 3) * 2;
#pragma unroll
    for (int im = 0; im < 2; im++) {
#pragma unroll
        for (int in = 0; in < 8; in++) {
            const int ncol = n0 + wn * 64 + in * 8 + c0;
            const float b0 = __ldg(&bias[ncol]);
            const float b1 = __ldg(&bias[ncol + 1]);
#pragma unroll
            for (int half = 0; half < 2; half++) {
                const int mrow = m0 + wm * 32 + im * 16 + r0 + half * 8;
                float v0 = acc[im][in][half * 2]     + b0;
                float v1 = acc[im][in][half * 2 + 1] + b1;
                if (act == 1)      { v0 = gelu_f(v0);     v1 = gelu_f(v1); }
                else if (act == 2) { v0 = softplus_f(v0); v1 = softplus_f(v1); }
                if (outmode == 0) {
                    *(float2*)(Cf + (size_t)mrow * DIM + ncol) = make_float2(v0, v1);
                } else {
                    *(__half2*)(Ch + (size_t)mrow * DIM + ncol) =
                        __halves2half2(__float2half_rn(v0), __float2half_rn(v1));
                }
            }
        }
    }
}

// ---------------------------------------------------------------------------
// Tensor-core attention pass 1: A[n][m] += sum_c q[c][n] k[c][m]
// grid (64 bh, NCHUNK), 128 threads (4 warps, warp = 16 n-rows x 64 m-cols).
// q,k fp16 [token][dim]; trans-ldmatrix to get [dim][token] fragments.
// ---------------------------------------------------------------------------
#define P1_STAGE 16384   // q 8KB + k 8KB
#define P1_SMEM (2 * P1_STAGE)

__global__ __launch_bounds__(128)
void attn_pass1t(const __half* __restrict__ q, const __half* __restrict__ k,
                 float* __restrict__ Ap)
{
    extern __shared__ char smem[];
    const uint32_t sb = smem_u32(smem);
    const int bh = blockIdx.x, ch = blockIdx.y;
    const int b = bh >> 4, h = bh & 15;
    const __half* qb = q + (size_t)b * NTOK * DIM + h * HD;
    const __half* kb = k + (size_t)b * NTOK * DIM + h * HD;
    const int t = threadIdx.x, lane = t & 31, w = t >> 5;
    const int lu = t & 7, lr0 = t >> 3;       // loader: 16 rows x 8 units
    const int cbase = ch * (NTOK / NCHUNK);

    auto issue = [&](int stage, int it) {
        const uint32_t sbq = sb + stage * P1_STAGE;
        const uint32_t sbk = sbq + 8192;
        const int c0 = cbase + it * 64;
#pragma unroll
        for (int i = 0; i < 4; i++) {
            const int row = lr0 + i * 16;
            const uint32_t so = SWZ((uint32_t)(row * 128 + lu * 16));
            cp16(sbq + so, qb + (size_t)(c0 + row) * DIM + lu * 8);
            cp16(sbk + so, kb + (size_t)(c0 + row) * DIM + lu * 8);
        }
        CP_COMMIT();
    };

    issue(0, 0);
    issue(1, 1);

    float acc[8][4];
#pragma unroll
    for (int in = 0; in < 8; in++)
#pragma unroll
        for (int j = 0; j < 4; j++) acc[in][j] = 0.0f;

    const int g  = lane >> 3, rr = lane & 7;
    const int toksel = ((g >> 1) << 3) + rr;   // token offset within k16 block
    const int dimsel = (g & 1) << 3;           // dim +0 / +8

    for (int it = 0; it < 16; it++) {
        if (it == 15) { CP_WAIT(0); } else { CP_WAIT(1); }
        __syncthreads();
        const uint32_t stq = sb + (it & 1) * P1_STAGE;
        const uint32_t stk = stq + 8192;
#pragma unroll
        for (int ks = 0; ks < 4; ks++) {
            const int tok = ks * 16 + toksel;
            uint32_t ah[4];
            LDSM4T(ah, stq + SWZ((uint32_t)(tok * 128 + (w * 16 + dimsel) * 2)));
            uint32_t bh2[8][2];
#pragma unroll
            for (int jb = 0; jb < 4; jb++) {
                uint32_t qh[4];
                LDSM4T(qh, stk + SWZ((uint32_t)(tok * 128 + (jb * 16 + dimsel) * 2)));
                bh2[2 * jb][0] = qh[0]; bh2[2 * jb][1] = qh[2];
                bh2[2 * jb + 1][0] = qh[1]; bh2[2 * jb + 1][1] = qh[3];
            }
#pragma unroll
            for (int in = 0; in < 8; in++)
                MMA16816F(acc[in], ah, bh2[in]);
        }
        if (it + 2 < 16) { __syncthreads(); issue(it & 1, it + 2); }
    }

    // write partials: A[n][m], n = w*16 + r0 + half*8, m = in*8 + pair
    const int r0 = lane >> 2, cp = (lane & 3) * 2;
    float* Abh = Ap + ((size_t)ch * 64 + bh) * (HD * HD);
#pragma unroll
    for (int in = 0; in < 8; in++) {
        const int m = in * 8 + cp;
#pragma unroll
        for (int half = 0; half < 2; half++) {
            const int n = w * 16 + r0 + half * 8;
            *(float2*)(Abh + n * 64 + m) =
                make_float2(acc[in][half * 2], acc[in][half * 2 + 1]);
        }
    }
}

// ---------------------------------------------------------------------------
// Reduce partials -> A fp16 [n][m] + z[n] = 1/(SCALE*rowsum(A)+DIM)
// ---------------------------------------------------------------------------
__global__ __launch_bounds__(256)
void attn_reduce(const float* __restrict__ Ap, __half* __restrict__ Ah,
                 float* __restrict__ gZ)
{
    const int bh = blockIdx.x, t = threadIdx.x;
    const int row = t >> 2, qp = t & 3;       // 64 rows x 4 quarters
    float s[16];
#pragma unroll
    for (int j = 0; j < 16; j++) s[j] = 0.0f;
    for (int c = 0; c < NCHUNK; c++) {
        const float* p = Ap + ((size_t)c * 64 + bh) * (HD * HD) + row * 64 + qp * 16;
#pragma unroll
        for (int j = 0; j < 16; j += 4) {
            float4 v4 = *(const float4*)(p + j);
            s[j] += v4.x; s[j + 1] += v4.y; s[j + 2] += v4.z; s[j + 3] += v4.w;
        }
    }
    alignas(16) __half hv[16];
    float rp = 0.0f;
#pragma unroll
    for (int j = 0; j < 16; j++) { rp += s[j]; hv[j] = __float2half_rn(s[j]); }
    uint4* dst = (uint4*)(Ah + (size_t)bh * (HD * HD) + row * 64 + qp * 16);
    dst[0] = ((uint4*)hv)[0];
    dst[1] = ((uint4*)hv)[1];
    rp += __shfl_xor_sync(0xffffffffu, rp, 1);
    rp += __shfl_xor_sync(0xffffffffu, rp, 2);
    if (qp == 0)
        gZ[bh * HD + row] = 1.0f / (SCALE * rp + (float)DIM);
}

// ---------------------------------------------------------------------------
// Tensor-core attention pass 2: out[d][n] = (SCALE*sum_m v[d][m]A[n][m] + v[d][n])
//                                          * z[n] * g[d][n], scramble-written.
// grid (64 bh, 64 token-chunks), 128 threads.
// ---------------------------------------------------------------------------
__global__ __launch_bounds__(128)
void attn_pass2t(const __half* __restrict__ v, const __half* __restrict__ gg,
                 const __half* __restrict__ Ah, const float* __restrict__ gZ,
                 __half* __restrict__ Yh)
{
    __shared__ __align__(16) char As_s[8192];
    __shared__ __align__(16) char vs_s[8192];
    __shared__ float zs[64];
    const int bh = blockIdx.x, b = bh >> 4, h = bh & 15;
    const int c0 = blockIdx.y * 64;
    const int t = threadIdx.x, lane = t & 31, w = t >> 5;
    const uint32_t sA = smem_u32(As_s), sV = smem_u32(vs_s);

    {
        const uint4* Ag = (const uint4*)(Ah + (size_t)bh * (HD * HD));
        const __half* vb = v + (size_t)(b * NTOK + c0) * DIM + h * HD;
        for (int i = t; i < 512; i += 128) {
            const int row = i >> 3, un = i & 7;
            const uint32_t so = SWZ((uint32_t)(row * 128 + un * 16));
            *(uint4*)(As_s + so) = Ag[i];
            *(uint4*)(vs_s + so) = *(const uint4*)(vb + (size_t)row * DIM + un * 8);
        }
        if (t < 64) zs[t] = gZ[bh * HD + t];
    }
    __syncthreads();

    float acc[8][4];
#pragma unroll
    for (int in = 0; in < 8; in++)
#pragma unroll
        for (int j = 0; j < 4; j++) acc[in][j] = 0.0f;

    const int g = lane >> 3, rr = lane & 7;
#pragma unroll
    for (int ks = 0; ks < 4; ks++) {
        const int ku = ks * 2 + (g >> 1);
        uint32_t ah[4];
        {
            const int row = w * 16 + ((g & 1) << 3) + rr;
            LDSM4(ah, sV + SWZ((uint32_t)(row * 128 + ku * 16)));
        }
        uint32_t bh2[8][2];
#pragma unroll
        for (int jb = 0; jb < 4; jb++) {
            const int row = jb * 16 + ((g & 1) << 3) + rr;
            uint32_t qh[4];
            LDSM4(qh, sA + SWZ((uint32_t)(row * 128 + ku * 16)));
            bh2[2 * jb][0] = qh[0]; bh2[2 * jb][1] = qh[2];
            bh2[2 * jb + 1][0] = qh[1]; bh2[2 * jb + 1][1] = qh[3];
        }
#pragma unroll
        for (int in = 0; in < 8; in++)
            MMA16816F(acc[in], ah, bh2[in]);
    }

    const int r0 = lane >> 2, cp = (lane & 3) * 2;
#pragma unroll
    for (int in = 0; in < 8; in++) {
        const int n = in * 8 + cp;
#pragma unroll
        for (int half = 0; half < 2; half++) {
            const int dl = w * 16 + r0 + half * 8;
            const int tok = c0 + dl;
            __half2 vv = *(__half2*)(vs_s + SWZ((uint32_t)(dl * 128 + n * 2)));
            float2 vf = __half22float2(vv);
            __half2 gv = *(const __half2*)(gg + (size_t)(b * NTOK + tok) * DIM + h * HD + n);
            float2 gf = __half22float2(gv);
            float o0 = (SCALE * acc[in][half * 2]     + vf.x) * zs[n]     * gf.x;
            float o1 = (SCALE * acc[in][half * 2 + 1] + vf.y) * zs[n + 1] * gf.y;
            const int row = b * NTOK + h * 256 + (tok >> 4);
            const int col = ((tok & 15) << 6) + n;
            *(__half2*)(Yh + (size_t)row * DIM + col) =
                __halves2half2(__float2half_rn(o0), __float2half_rn(o1));
        }
    }
}

// ---------------------------------------------------------------------------
// Launch — R14 DAG with tensor-core attention
// ---------------------------------------------------------------------------
extern "C" void kernel_launch(void* const* d_in, const int* in_sizes, int n_in,
                              void* d_out, int out_size)
{
    const float* x    = (const float*)d_in[0];
    const float* q_w1 = (const float*)d_in[1];
    const float* q_b1 = (const float*)d_in[2];
    const float* q_w2 = (const float*)d_in[3];
    const float* q_b2 = (const float*)d_in[4];
    const float* k_w1 = (const float*)d_in[5];
    const float* k_b1 = (const float*)d_in[6];
    const float* k_w2 = (const float*)d_in[7];
    const float* k_b2 = (const float*)d_in[8];
    const float* v_w  = (const float*)d_in[9];
    const float* v_b  = (const float*)d_in[10];
    const float* g_w  = (const float*)d_in[11];
    const float* g_b  = (const float*)d_in[12];
    const float* p_w  = (const float*)d_in[13];
    const float* p_b  = (const float*)d_in[14];
    float* out = (float*)d_out;

    __half *xh, *hqh, *hkh, *yh, *wh, *qb, *kb, *vb, *gb, *Ahp;
    float *zb, *Apb;
    cudaGetSymbolAddress((void**)&xh,  g_x_h);
    cudaGetSymbolAddress((void**)&hqh, g_hq_h);
    cudaGetSymbolAddress((void**)&hkh, g_hk_h);
    cudaGetSymbolAddress((void**)&yh,  g_y_h);
    cudaGetSymbolAddress((void**)&wh,  g_w_h);
    cudaGetSymbolAddress((void**)&qb,  g_q);
    cudaGetSymbolAddress((void**)&kb,  g_k);
    cudaGetSymbolAddress((void**)&vb,  g_v);
    cudaGetSymbolAddress((void**)&gb,  g_g);
    cudaGetSymbolAddress((void**)&Ahp, g_A_h);
    cudaGetSymbolAddress((void**)&zb,  g_z);
    cudaGetSymbolAddress((void**)&Apb, g_Ap);

    static bool init_done = false;
    static cudaStream_t s1, s2, s3;
    static cudaEvent_t ev_fork, ev_x, ev_qw, ev_k2, ev_v, ev_g, ev_pw;
    if (!init_done) {
        cudaFuncSetAttribute(gemm_mma, cudaFuncAttributeMaxDynamicSharedMemorySize, GSMEM_TOTAL);
        cudaStreamCreateWithFlags(&s1, cudaStreamNonBlocking);
        cudaStreamCreateWithFlags(&s2, cudaStreamNonBlocking);
        cudaStreamCreateWithFlags(&s3, cudaStreamNonBlocking);
        cudaEventCreateWithFlags(&ev_fork, cudaEventDisableTiming);
        cudaEventCreateWithFlags(&ev_x,    cudaEventDisableTiming);
        cudaEventCreateWithFlags(&ev_qw,   cudaEventDisableTiming);
        cudaEventCreateWithFlags(&ev_k2,   cudaEventDisableTiming);
        cudaEventCreateWithFlags(&ev_v,    cudaEventDisableTiming);
        cudaEventCreateWithFlags(&ev_g,    cudaEventDisableTiming);
        cudaEventCreateWithFlags(&ev_pw,   cudaEventDisableTiming);
        init_done = true;
    }

    const int WSZ = DIM * DIM;
    const int W8  = WSZ / 8;
#define WH(i) (wh + (size_t)(i) * WSZ)

    dim3 ggrid(DIM / 128, MROWS / 128);   // (8, 128)

    // === fork ===
    cudaEventRecord(ev_fork, 0);
    cudaStreamWaitEvent(s1, ev_fork, 0);
    cudaStreamWaitEvent(s2, ev_fork, 0);
    cudaStreamWaitEvent(s3, ev_fork, 0);

    // --- weight conversions ---
    conv_f2h_w<<<592, 256, 0, s1>>>((const float4*)k_w1, (uint4*)WH(2), W8);
    conv_f2h_w<<<592, 256, 0, s1>>>((const float4*)k_w2, (uint4*)WH(3), W8);
    conv_f2h_w<<<592, 256, 0, s2>>>((const float4*)q_w1, (uint4*)WH(0), W8);
    conv_f2h_w<<<592, 256, 0, s2>>>((const float4*)q_w2, (uint4*)WH(1), W8);
    cudaEventRecord(ev_qw, s2);
    conv_f2h_w<<<592, 256, 0, s2>>>((const float4*)v_w,  (uint4*)WH(4), W8);
    conv_f2h_w<<<592, 256, 0, s3>>>((const float4*)g_w,  (uint4*)WH(5), W8);
    conv_f2h_w<<<592, 256, 0, s3>>>((const float4*)p_w,  (uint4*)WH(6), W8);
    cudaEventRecord(ev_pw, s3);

    // s0: x convert (critical head)
    conv_f2h_w<<<2048, 256>>>((const float4*)x, (uint4*)xh, MROWS * DIM / 8);
    cudaEventRecord(ev_x, 0);

    // --- q/k chains first ---
    cudaStreamWaitEvent(0, ev_qw, 0);
    gemm_mma<<<ggrid, 256, GSMEM_TOTAL>>>(xh, WH(0), q_b1, 1, 1, nullptr, hqh);
    cudaStreamWaitEvent(s1, ev_x, 0);
    gemm_mma<<<ggrid, 256, GSMEM_TOTAL, s1>>>(xh, WH(2), k_b1, 1, 1, nullptr, hkh);
    gemm_mma<<<ggrid, 256, GSMEM_TOTAL>>>(hqh, WH(1), q_b2, 2, 1, nullptr, qb);
    gemm_mma<<<ggrid, 256, GSMEM_TOTAL, s1>>>(hkh, WH(3), k_b2, 2, 1, nullptr, kb);
    cudaEventRecord(ev_k2, s1);

    // --- v, g GEMMs trail (overlap with attention pass 1) ---
    cudaStreamWaitEvent(s2, ev_x, 0);
    gemm_mma<<<ggrid, 256, GSMEM_TOTAL, s2>>>(xh, WH(4), v_b, 1, 1, nullptr, vb);
    cudaEventRecord(ev_v, s2);
    cudaStreamWaitEvent(s3, ev_x, 0);
    gemm_mma<<<ggrid, 256, GSMEM_TOTAL, s3>>>(xh, WH(5), g_b, 1, 1, nullptr, gb);
    cudaEventRecord(ev_g, s3);

    // --- attention (tensor-core) ---
    cudaStreamWaitEvent(0, ev_k2, 0);
    attn_pass1t<<<dim3(BATCH * NHEAD, NCHUNK), 128, P1_SMEM>>>(qb, kb, Apb);
    attn_reduce<<<BATCH * NHEAD, 256>>>(Apb, Ahp, zb);

    cudaStreamWaitEvent(0, ev_v, 0);
    cudaStreamWaitEvent(0, ev_g, 0);
    attn_pass2t<<<dim3(BATCH * NHEAD, NTOK / 64), 128>>>(vb, gb, Ahp, zb, yh);

    // --- final projection ---
    cudaStreamWaitEvent(0, ev_pw, 0);
    gemm_mma<<<ggrid, 256, GSMEM_TOTAL>>>(yh, WH(6), p_b, 0, 0, out, nullptr);
}